// round 3
// baseline (speedup 1.0000x reference)
#include <cuda_runtime.h>
#include <math.h>

#define B_    256
#define T_    64
#define STOCH 128
#define DETD  512
#define HIDD  512
#define OBSD  1024
#define ACTD  32
#define BT    (B_*T_)
#define OUTW  1152

// Scratch (device globals; no allocation allowed)
__device__ float g_act_proj[BT*DETD];   // act @ prior_w1[:32] + prior_b1   (m = b*64+t)
__device__ float g_obs_proj[BT*HIDD];   // obs @ post_w1[512:] + post_b1

__device__ __forceinline__ float elu_f(float x)      { return x > 0.f ? x : expm1f(x); }
__device__ __forceinline__ float sigm_f(float x)     { return 1.f/(1.f+expf(-x)); }
__device__ __forceinline__ float softplus_f(float x) { return fmaxf(x,0.f) + log1pf(expf(-fabsf(x))); }

// ---------------------------------------------------------------------------
// Generic projection GEMM: C[m*512+n] = sum_k A[m*K+k]*W[k*512+n] + bias[n]
// M = BT, N = 512.  64x64 tile, BK=16, 256 threads, 4x4 microtile.
// ---------------------------------------------------------------------------
__global__ __launch_bounds__(256) void proj_gemm(
    const float* __restrict__ A, const float* __restrict__ W,
    const float* __restrict__ bias, float* __restrict__ C, int K)
{
    __shared__ __align__(16) float Ast[16][68];  // [k][m], padded
    __shared__ __align__(16) float Bs[16][64];   // [k][n]

    const int tid = threadIdx.x;
    const int m0 = blockIdx.y * 64;
    const int n0 = blockIdx.x * 64;
    const int tx = tid & 15, ty = tid >> 4;

    const int arow = tid >> 2;           // 0..63
    const int avec = (tid & 3) * 4;      // 0,4,8,12
    const int bk   = tid >> 4;           // 0..15
    const int bn   = (tid & 15) * 4;

    float acc[4][4];
    #pragma unroll
    for (int i = 0; i < 4; i++)
        #pragma unroll
        for (int j = 0; j < 4; j++) acc[i][j] = 0.f;

    for (int k0 = 0; k0 < K; k0 += 16) {
        float4 av = *(const float4*)&A[(m0 + arow) * K + k0 + avec];
        Ast[avec+0][arow] = av.x;
        Ast[avec+1][arow] = av.y;
        Ast[avec+2][arow] = av.z;
        Ast[avec+3][arow] = av.w;
        float4 bv = *(const float4*)&W[(k0 + bk) * 512 + n0 + bn];
        *(float4*)&Bs[bk][bn] = bv;
        __syncthreads();
        #pragma unroll
        for (int kk = 0; kk < 16; kk++) {
            float4 a4 = *(const float4*)&Ast[kk][ty*4];
            float4 b4 = *(const float4*)&Bs[kk][tx*4];
            float a[4] = {a4.x, a4.y, a4.z, a4.w};
            float b[4] = {b4.x, b4.y, b4.z, b4.w};
            #pragma unroll
            for (int i = 0; i < 4; i++)
                #pragma unroll
                for (int j = 0; j < 4; j++) acc[i][j] += a[i]*b[j];
        }
        __syncthreads();
    }

    #pragma unroll
    for (int i = 0; i < 4; i++) {
        int m = m0 + ty*4 + i;
        #pragma unroll
        for (int j = 0; j < 4; j++) {
            int n = n0 + tx*4 + j;
            C[m*512 + n] = acc[i][j] + bias[n];
        }
    }
}

// ---------------------------------------------------------------------------
// Persistent recurrence kernel: 64 CTAs, each owns 4 batch rows, runs all 64
// steps locally. Activations in SMEM (transposed [col][row] for float4
// broadcast reads), weights streamed from L2 each step.
// NOTE on GRU semantics: the reference's `r * h @ Wh` parses as (r*h) @ Wh
// (Python: * and @ same precedence, left-assoc) — classic GRU, reset BEFORE
// the candidate matmul. Stage order: zr gates -> rh = r*det -> ah = rh@Wh_a.
// SMEM layout (floats):
//   stochT 128*4 | detT 512*4 | x1T 512*4 | x3T 512*4 | zsT 1024*4
//   axT 512*4 | rhT 512*4 | qT 256*4        total 15872 floats = 63488 B
// ---------------------------------------------------------------------------
#define SMEM_REC (15872*4)

__global__ __launch_bounds__(256) void rssm_recur(
    const float* __restrict__ prior_w1,   // 160x512 (rows 32..159 = stoch part)
    const float* __restrict__ gru_wi,     // 512x1536
    const float* __restrict__ gru_wh,     // 512x1536
    const float* __restrict__ gru_b,      // 1536
    const float* __restrict__ post_w1,    // 1536x512 (rows 0..511 = det part)
    const float* __restrict__ post_w2,    // 512x256
    const float* __restrict__ post_b2,    // 256
    const float* __restrict__ noise_post, // B,T,128
    float* __restrict__ out)              // B,T,1152
{
    extern __shared__ __align__(16) float sm[];
    float* stochT = sm;                 // [128][4]
    float* detT   = stochT + 128*4;     // [512][4]
    float* x1T    = detT   + 512*4;     // [512][4]
    float* x3T    = x1T    + 512*4;     // [512][4]
    float* zsT    = x3T    + 512*4;     // [1024][4]  z: cols 0..511, r: 512..1023
    float* axT    = zsT    + 1024*4;    // [512][4]   ax = x1@Wi_a + b_a
    float* rhT    = axT    + 512*4;     // [512][4]   rh = r .* det(old)
    float* qT     = rhT    + 512*4;     // [256][4]

    const int tid = threadIdx.x;
    const int b0  = blockIdx.x * 4;
    const float* W1s = prior_w1 + 32*512;

    for (int i = tid; i < 128*4; i += 256) stochT[i] = 0.f;
    for (int i = tid; i < 512*4; i += 256) detT[i]   = 0.f;
    __syncthreads();

    for (int t = 0; t < T_; t++) {
        // ---- S0: x1 = elu(act_proj + stoch @ W1s) ------------------------
        {
            const int n = tid * 2;
            float acc[2][4];
            #pragma unroll
            for (int j = 0; j < 2; j++)
                #pragma unroll
                for (int r = 0; r < 4; r++) acc[j][r] = 0.f;
            #pragma unroll 4
            for (int k = 0; k < 128; k++) {
                float4 s4 = ((const float4*)stochT)[k];
                float2 w  = *(const float2*)(W1s + k*512 + n);
                float sa[4] = {s4.x, s4.y, s4.z, s4.w};
                float wa[2] = {w.x, w.y};
                #pragma unroll
                for (int j = 0; j < 2; j++)
                    #pragma unroll
                    for (int r = 0; r < 4; r++) acc[j][r] += sa[r]*wa[j];
            }
            #pragma unroll
            for (int j = 0; j < 2; j++) {
                float4 v;
                v.x = elu_f(acc[j][0] + g_act_proj[((b0+0)*64 + t)*512 + n + j]);
                v.y = elu_f(acc[j][1] + g_act_proj[((b0+1)*64 + t)*512 + n + j]);
                v.z = elu_f(acc[j][2] + g_act_proj[((b0+2)*64 + t)*512 + n + j]);
                v.w = elu_f(acc[j][3] + g_act_proj[((b0+3)*64 + t)*512 + n + j]);
                ((float4*)x1T)[n + j] = v;
            }
        }
        __syncthreads();
        // ---- S1a: zr gates (cols 0..1023) + ax (a-cols, no r dependency) --
        {   // zr = sigmoid(x1@Wi[:, :1024] + det@Wh[:, :1024] + b[:1024])
            const int n = tid * 4;
            float acc[4][4];
            #pragma unroll
            for (int j = 0; j < 4; j++)
                #pragma unroll
                for (int r = 0; r < 4; r++) acc[j][r] = 0.f;
            #pragma unroll 4
            for (int k = 0; k < 512; k++) {
                float4 x4 = ((const float4*)x1T)[k];
                float4 d4 = ((const float4*)detT)[k];
                float4 wi = *(const float4*)(gru_wi + k*1536 + n);
                float4 wh = *(const float4*)(gru_wh + k*1536 + n);
                float xa[4] = {x4.x, x4.y, x4.z, x4.w};
                float da[4] = {d4.x, d4.y, d4.z, d4.w};
                float wia[4] = {wi.x, wi.y, wi.z, wi.w};
                float wha[4] = {wh.x, wh.y, wh.z, wh.w};
                #pragma unroll
                for (int j = 0; j < 4; j++)
                    #pragma unroll
                    for (int r = 0; r < 4; r++)
                        acc[j][r] += xa[r]*wia[j] + da[r]*wha[j];
            }
            #pragma unroll
            for (int j = 0; j < 4; j++) {
                float b = gru_b[n + j];
                float4 v;
                v.x = sigm_f(acc[j][0] + b);
                v.y = sigm_f(acc[j][1] + b);
                v.z = sigm_f(acc[j][2] + b);
                v.w = sigm_f(acc[j][3] + b);
                ((float4*)zsT)[n + j] = v;
            }
        }
        {   // ax = x1 @ Wi[:, 1024:] + b[1024:]
            const int n = tid * 2;
            float ax[2][4];
            #pragma unroll
            for (int j = 0; j < 2; j++)
                #pragma unroll
                for (int r = 0; r < 4; r++) ax[j][r] = 0.f;
            #pragma unroll 4
            for (int k = 0; k < 512; k++) {
                float4 x4 = ((const float4*)x1T)[k];
                float2 wi = *(const float2*)(gru_wi + k*1536 + 1024 + n);
                float xa[4] = {x4.x, x4.y, x4.z, x4.w};
                float wia[2] = {wi.x, wi.y};
                #pragma unroll
                for (int j = 0; j < 2; j++)
                    #pragma unroll
                    for (int r = 0; r < 4; r++) ax[j][r] += xa[r]*wia[j];
            }
            #pragma unroll
            for (int j = 0; j < 2; j++) {
                float b = gru_b[1024 + n + j];
                float4 v = {ax[j][0]+b, ax[j][1]+b, ax[j][2]+b, ax[j][3]+b};
                ((float4*)axT)[n + j] = v;
            }
        }
        __syncthreads();
        // ---- S1b: rh = r .* det(old) -------------------------------------
        {
            #pragma unroll
            for (int jj = 0; jj < 2; jj++) {
                int j = tid * 2 + jj;
                float4 r4 = ((const float4*)zsT)[512 + j];
                float4 d4 = ((const float4*)detT)[j];
                float4 v = {r4.x*d4.x, r4.y*d4.y, r4.z*d4.z, r4.w*d4.w};
                ((float4*)rhT)[j] = v;
            }
        }
        __syncthreads();
        // ---- S1c: ah = rh @ Wh[:, 1024:]; combine gates -> det_new --------
        {
            const int n = tid * 2;
            float ah[2][4];
            #pragma unroll
            for (int j = 0; j < 2; j++)
                #pragma unroll
                for (int r = 0; r < 4; r++) ah[j][r] = 0.f;
            #pragma unroll 4
            for (int k = 0; k < 512; k++) {
                float4 h4 = ((const float4*)rhT)[k];
                float2 wh = *(const float2*)(gru_wh + k*1536 + 1024 + n);
                float ha[4] = {h4.x, h4.y, h4.z, h4.w};
                float wha[2] = {wh.x, wh.y};
                #pragma unroll
                for (int j = 0; j < 2; j++)
                    #pragma unroll
                    for (int r = 0; r < 4; r++) ah[j][r] += ha[r]*wha[j];
            }
            // combine: each thread owns cols n, n+1 exclusively (no race on detT)
            float dn2[2][4];
            #pragma unroll
            for (int j = 0; j < 2; j++) {
                float4 z4 = ((const float4*)zsT)[n + j];
                float4 a4 = ((const float4*)axT)[n + j];
                float4 d4 = ((const float4*)detT)[n + j];
                float z[4] = {z4.x, z4.y, z4.z, z4.w};
                float ax[4] = {a4.x, a4.y, a4.z, a4.w};
                float d[4] = {d4.x, d4.y, d4.z, d4.w};
                float4 dn;
                float* dnp = (float*)&dn;
                #pragma unroll
                for (int rr = 0; rr < 4; rr++) {
                    float av = tanhf(ax[rr] + ah[j][rr]);
                    float nd = (1.f - z[rr])*d[rr] + z[rr]*av;
                    dnp[rr] = nd;
                    dn2[j][rr] = nd;
                }
                ((float4*)detT)[n + j] = dn;
            }
            #pragma unroll
            for (int rr = 0; rr < 4; rr++) {
                int base = ((b0 + rr)*64 + t)*OUTW + 128 + n;
                float2 v = {dn2[0][rr], dn2[1][rr]};
                *(float2*)&out[base] = v;
            }
        }
        __syncthreads();
        // ---- S2: x3 = elu(obs_proj + det @ post_w1[:512]) ----------------
        {
            const int n = tid * 2;
            float acc[2][4];
            #pragma unroll
            for (int j = 0; j < 2; j++)
                #pragma unroll
                for (int r = 0; r < 4; r++) acc[j][r] = 0.f;
            #pragma unroll 4
            for (int k = 0; k < 512; k++) {
                float4 d4 = ((const float4*)detT)[k];
                float2 w  = *(const float2*)(post_w1 + k*512 + n);
                float da[4] = {d4.x, d4.y, d4.z, d4.w};
                float wa[2] = {w.x, w.y};
                #pragma unroll
                for (int j = 0; j < 2; j++)
                    #pragma unroll
                    for (int r = 0; r < 4; r++) acc[j][r] += da[r]*wa[j];
            }
            #pragma unroll
            for (int j = 0; j < 2; j++) {
                float4 v;
                v.x = elu_f(acc[j][0] + g_obs_proj[((b0+0)*64 + t)*512 + n + j]);
                v.y = elu_f(acc[j][1] + g_obs_proj[((b0+1)*64 + t)*512 + n + j]);
                v.z = elu_f(acc[j][2] + g_obs_proj[((b0+2)*64 + t)*512 + n + j]);
                v.w = elu_f(acc[j][3] + g_obs_proj[((b0+3)*64 + t)*512 + n + j]);
                ((float4*)x3T)[n + j] = v;
            }
        }
        __syncthreads();
        // ---- S3: q = x3 @ post_w2 + b2 -----------------------------------
        {
            const int n = tid;  // 0..255
            float acc[4] = {0.f, 0.f, 0.f, 0.f};
            #pragma unroll 4
            for (int k = 0; k < 512; k++) {
                float4 x4 = ((const float4*)x3T)[k];
                float w = post_w2[k*256 + n];
                acc[0] += x4.x*w; acc[1] += x4.y*w;
                acc[2] += x4.z*w; acc[3] += x4.w*w;
            }
            float b2 = post_b2[n];
            float4 q = {acc[0]+b2, acc[1]+b2, acc[2]+b2, acc[3]+b2};
            ((float4*)qT)[n] = q;
        }
        __syncthreads();
        // ---- S3b: stats, sample posterior stoch, write outputs -----------
        if (tid < 128) {
            const int j = tid;
            float4 qm4 = ((const float4*)qT)[j];
            float4 qr4 = ((const float4*)qT)[128 + j];
            float qm[4] = {qm4.x, qm4.y, qm4.z, qm4.w};
            float qs[4];
            qs[0] = softplus_f(qr4.x) + 0.1f;
            qs[1] = softplus_f(qr4.y) + 0.1f;
            qs[2] = softplus_f(qr4.z) + 0.1f;
            qs[3] = softplus_f(qr4.w) + 0.1f;
            float4 st;
            float* stp = (float*)&st;
            #pragma unroll
            for (int rr = 0; rr < 4; rr++) {
                float nq = noise_post[((b0 + rr)*64 + t)*128 + j];
                float s = qm[rr] + qs[rr]*nq;
                stp[rr] = s;
                int base = ((b0 + rr)*64 + t)*OUTW;
                out[base + j]        = s;
                out[base + 896 + j]  = qm[rr];
                out[base + 1024 + j] = qs[rr];
            }
            ((float4*)stochT)[j] = st;
        }
        __syncthreads();
    }
}

// ---------------------------------------------------------------------------
// Deferred prior branch (batched over all B*T rows):
//   xp = elu(det @ prior_w2 + b2); [pm|s] = xp @ prior_w3 + b3
//   ps = softplus(s)+0.1.   Reads det from out[.,128:640], writes out[.,640:896].
// ---------------------------------------------------------------------------
#define SMEM_PRI (2*32*513*4)

__global__ __launch_bounds__(256) void prior_branch(
    const float* __restrict__ pw2, const float* __restrict__ pb2,
    const float* __restrict__ pw3, const float* __restrict__ pb3,
    float* __restrict__ out)
{
    extern __shared__ __align__(16) float sm2[];
    float* As = sm2;             // [32][513]
    float* Xp = sm2 + 32*513;    // [32][513]

    const int tid = threadIdx.x;
    const int m0  = blockIdx.x * 32;

    for (int i = tid; i < 32*512; i += 256) {
        int r = i >> 9, c = i & 511;
        As[r*513 + c] = out[(m0 + r)*OUTW + 128 + c];
    }
    __syncthreads();

    const int rw = tid >> 6;   // 0..3  -> rows rw*8..rw*8+7
    const int nc = tid & 63;   // 0..63

    {   // GEMM1: Xp[32][512]
        float acc[8][8];
        #pragma unroll
        for (int i = 0; i < 8; i++)
            #pragma unroll
            for (int j = 0; j < 8; j++) acc[i][j] = 0.f;
        #pragma unroll 2
        for (int k = 0; k < 512; k++) {
            float a[8];
            #pragma unroll
            for (int i = 0; i < 8; i++) a[i] = As[(rw*8 + i)*513 + k];
            float4 w0 = *(const float4*)&pw2[k*512 + nc*8];
            float4 w1 = *(const float4*)&pw2[k*512 + nc*8 + 4];
            float w[8] = {w0.x, w0.y, w0.z, w0.w, w1.x, w1.y, w1.z, w1.w};
            #pragma unroll
            for (int i = 0; i < 8; i++)
                #pragma unroll
                for (int j = 0; j < 8; j++) acc[i][j] += a[i]*w[j];
        }
        #pragma unroll
        for (int i = 0; i < 8; i++)
            #pragma unroll
            for (int j = 0; j < 8; j++)
                Xp[(rw*8 + i)*513 + nc*8 + j] = elu_f(acc[i][j] + pb2[nc*8 + j]);
    }
    __syncthreads();
    {   // GEMM2: [32][256] -> pm/ps
        float acc[8][4];
        #pragma unroll
        for (int i = 0; i < 8; i++)
            #pragma unroll
            for (int j = 0; j < 4; j++) acc[i][j] = 0.f;
        #pragma unroll 2
        for (int k = 0; k < 512; k++) {
            float a[8];
            #pragma unroll
            for (int i = 0; i < 8; i++) a[i] = Xp[(rw*8 + i)*513 + k];
            float4 w4 = *(const float4*)&pw3[k*256 + nc*4];
            float w[4] = {w4.x, w4.y, w4.z, w4.w};
            #pragma unroll
            for (int i = 0; i < 8; i++)
                #pragma unroll
                for (int j = 0; j < 4; j++) acc[i][j] += a[i]*w[j];
        }
        #pragma unroll
        for (int i = 0; i < 8; i++) {
            int m = m0 + rw*8 + i;
            #pragma unroll
            for (int j = 0; j < 4; j++) {
                int c = nc*4 + j;
                float v = acc[i][j] + pb3[c];
                if (c < 128) out[m*OUTW + 640 + c] = v;                       // pm
                else         out[m*OUTW + 768 + (c - 128)] = softplus_f(v) + 0.1f; // ps
            }
        }
    }
}

// ---------------------------------------------------------------------------
extern "C" void kernel_launch(void* const* d_in, const int* in_sizes, int n_in,
                              void* d_out, int out_size)
{
    const float* observations = (const float*)d_in[0];
    const float* actions      = (const float*)d_in[1];
    // d_in[2] = noise_prior: unused (prior sample is dead in the reference)
    const float* noise_post   = (const float*)d_in[3];
    const float* prior_w1     = (const float*)d_in[4];
    const float* prior_b1     = (const float*)d_in[5];
    const float* gru_wi       = (const float*)d_in[6];
    const float* gru_wh       = (const float*)d_in[7];
    const float* gru_b        = (const float*)d_in[8];
    const float* prior_w2     = (const float*)d_in[9];
    const float* prior_b2     = (const float*)d_in[10];
    const float* prior_w3     = (const float*)d_in[11];
    const float* prior_b3     = (const float*)d_in[12];
    const float* post_w1      = (const float*)d_in[13];
    const float* post_b1      = (const float*)d_in[14];
    const float* post_w2      = (const float*)d_in[15];
    const float* post_b2      = (const float*)d_in[16];
    float* out = (float*)d_out;

    float *actp, *obsp;
    cudaGetSymbolAddress((void**)&actp, g_act_proj);
    cudaGetSymbolAddress((void**)&obsp, g_obs_proj);

    cudaFuncSetAttribute(rssm_recur, cudaFuncAttributeMaxDynamicSharedMemorySize, SMEM_REC);
    cudaFuncSetAttribute(prior_branch, cudaFuncAttributeMaxDynamicSharedMemorySize, SMEM_PRI);

    // Batched precompute (off the critical path)
    proj_gemm<<<dim3(8, BT/64), 256>>>(actions, prior_w1, prior_b1, actp, ACTD);
    proj_gemm<<<dim3(8, BT/64), 256>>>(observations, post_w1 + 512*512, post_b1, obsp, OBSD);
    // Sequential recurrence: 64 CTAs x 4 rows, all 64 steps in one launch
    rssm_recur<<<64, 256, SMEM_REC>>>(prior_w1, gru_wi, gru_wh, gru_b,
                                      post_w1, post_w2, post_b2, noise_post, out);
    // Deferred prior head, batched over all B*T rows
    prior_branch<<<BT/32, 256, SMEM_PRI>>>(prior_w2, prior_b2, prior_w3, prior_b3, out);
}

// round 4
// speedup vs baseline: 2.1964x; 2.1964x over previous
#include <cuda_runtime.h>
#include <math.h>
#include <stdint.h>

#define B_    256
#define T_    64
#define STOCH 128
#define DETD  512
#define HIDD  512
#define OBSD  1024
#define ACTD  32
#define BT    (B_*T_)
#define OUTW  1152

// Scratch (device globals; no allocation allowed)
__device__ float g_act_proj[BT*DETD];   // act @ prior_w1[:32] + prior_b1   (m = b*64+t)
__device__ float g_obs_proj[BT*HIDD];   // obs @ post_w1[512:] + post_b1

__device__ __forceinline__ float elu_f(float x)      { return x > 0.f ? x : (__expf(x) - 1.f); }
__device__ __forceinline__ float sigm_f(float x)     { return 1.f/(1.f+__expf(-x)); }
__device__ __forceinline__ float softplus_f(float x) { return fmaxf(x,0.f) + log1pf(__expf(-fabsf(x))); }

__device__ __forceinline__ uint32_t smem_u32(const void* p) {
    uint32_t a;
    asm("{ .reg .u64 t; cvta.to.shared.u64 t, %1; cvt.u32.u64 %0, t; }" : "=r"(a) : "l"(p));
    return a;
}
__device__ __forceinline__ void st_peer_f4(uint32_t laddr, uint32_t peer, float4 v) {
    uint32_t ra;
    asm("mapa.shared::cluster.u32 %0, %1, %2;" : "=r"(ra) : "r"(laddr), "r"(peer));
    asm volatile("st.shared::cluster.f32 [%0],    %1;" :: "r"(ra), "f"(v.x));
    asm volatile("st.shared::cluster.f32 [%0+4],  %1;" :: "r"(ra), "f"(v.y));
    asm volatile("st.shared::cluster.f32 [%0+8],  %1;" :: "r"(ra), "f"(v.z));
    asm volatile("st.shared::cluster.f32 [%0+12], %1;" :: "r"(ra), "f"(v.w));
}
#define CLUSTER_SYNC() do { \
    asm volatile("barrier.cluster.arrive.aligned;" ::: "memory"); \
    asm volatile("barrier.cluster.wait.aligned;"   ::: "memory"); \
} while (0)

// ---------------------------------------------------------------------------
// Batched projection GEMM: C[m*512+n] = sum_k A[m*K+k]*W[k*512+n] + bias[n]
// ---------------------------------------------------------------------------
__global__ __launch_bounds__(256) void proj_gemm(
    const float* __restrict__ A, const float* __restrict__ W,
    const float* __restrict__ bias, float* __restrict__ C, int K)
{
    __shared__ __align__(16) float Ast[16][68];
    __shared__ __align__(16) float Bs[16][64];

    const int tid = threadIdx.x;
    const int m0 = blockIdx.y * 64;
    const int n0 = blockIdx.x * 64;
    const int tx = tid & 15, ty = tid >> 4;

    const int arow = tid >> 2;
    const int avec = (tid & 3) * 4;
    const int bk   = tid >> 4;
    const int bn   = (tid & 15) * 4;

    float acc[4][4];
    #pragma unroll
    for (int i = 0; i < 4; i++)
        #pragma unroll
        for (int j = 0; j < 4; j++) acc[i][j] = 0.f;

    for (int k0 = 0; k0 < K; k0 += 16) {
        float4 av = *(const float4*)&A[(m0 + arow) * K + k0 + avec];
        Ast[avec+0][arow] = av.x;
        Ast[avec+1][arow] = av.y;
        Ast[avec+2][arow] = av.z;
        Ast[avec+3][arow] = av.w;
        float4 bv = *(const float4*)&W[(k0 + bk) * 512 + n0 + bn];
        *(float4*)&Bs[bk][bn] = bv;
        __syncthreads();
        #pragma unroll
        for (int kk = 0; kk < 16; kk++) {
            float4 a4 = *(const float4*)&Ast[kk][ty*4];
            float4 b4 = *(const float4*)&Bs[kk][tx*4];
            float a[4] = {a4.x, a4.y, a4.z, a4.w};
            float b[4] = {b4.x, b4.y, b4.z, b4.w};
            #pragma unroll
            for (int i = 0; i < 4; i++)
                #pragma unroll
                for (int j = 0; j < 4; j++) acc[i][j] += a[i]*b[j];
        }
        __syncthreads();
    }

    #pragma unroll
    for (int i = 0; i < 4; i++) {
        int m = m0 + ty*4 + i;
        #pragma unroll
        for (int j = 0; j < 4; j++) {
            int n = n0 + tx*4 + j;
            C[m*512 + n] = acc[i][j] + bias[n];
        }
    }
}

// ---------------------------------------------------------------------------
// Persistent recurrence: 128 CTAs = 64 clusters of 2. Each cluster owns 4
// batch rows; within a cluster each CTA computes half the output columns and
// exchanges the 4KB activation halves via DSMEM + barrier.cluster.
// 512 threads/CTA; 256-col stages use K-split-2 + smem reduction.
// GRU note: reference's `r * h @ Wh` == (r*h) @ Wh (left-assoc).
// SMEM floats: stochT 512 | detT 2048 | x1T 2048 | x3T 2048 | zT 2048 |
//              axT 2048 | rhT 2048 | redT 2048   = 14848 (59392 B)
// ---------------------------------------------------------------------------
#define SMEM_REC (14848*4)

__global__ __launch_bounds__(512, 1) __cluster_dims__(2, 1, 1)
void rssm_recur(
    const float* __restrict__ prior_w1,   // 160x512
    const float* __restrict__ gru_wi,     // 512x1536
    const float* __restrict__ gru_wh,     // 512x1536
    const float* __restrict__ gru_b,      // 1536
    const float* __restrict__ post_w1,    // 1536x512 (rows 0..511 = det part)
    const float* __restrict__ post_w2,    // 512x256
    const float* __restrict__ post_b2,    // 256
    const float* __restrict__ noise_post, // B,T,128
    float* __restrict__ out)              // B,T,1152
{
    extern __shared__ __align__(16) float sm[];
    float* stochT = sm;            // [128][4]
    float* detT   = sm + 512;      // [512][4]
    float* x1T    = sm + 2560;     // [512][4]
    float* x3T    = sm + 4608;     // [512][4]
    float* zT     = sm + 6656;     // [512][4]
    float* axT    = sm + 8704;     // [512][4]
    float* rhT    = sm + 10752;    // [512][4]
    float* redT   = sm + 12800;    // [2][256][4]

    const int tid = threadIdx.x;
    uint32_t rank;
    asm("mov.u32 %0, %%cluster_ctarank;" : "=r"(rank));
    const uint32_t peer = rank ^ 1u;
    const int b0   = (blockIdx.x >> 1) * 4;
    const int j256 = tid & 255;
    const int kh   = tid >> 8;            // 0 or 1
    const int cOwn = (int)rank * 256 + j256;   // owned column for k-split stages
    const float* W1s = prior_w1 + 32*512;

    for (int i = tid; i < 512;  i += 512) stochT[i] = 0.f;
    for (int i = tid; i < 2048; i += 512) detT[i]   = 0.f;
    __syncthreads();
    CLUSTER_SYNC();

    for (int t = 0; t < T_; t++) {
        // ---- S0: x1 = elu(act_proj + stoch @ W1s)  (K-split 64/64) -------
        {
            float acc[4] = {0.f,0.f,0.f,0.f};
            const int kbeg = kh*64;
            #pragma unroll 8
            for (int k = kbeg; k < kbeg+64; k++) {
                float4 s4 = ((const float4*)stochT)[k];
                float w = W1s[k*512 + cOwn];
                acc[0] += s4.x*w; acc[1] += s4.y*w;
                acc[2] += s4.z*w; acc[3] += s4.w*w;
            }
            ((float4*)redT)[kh*256 + j256] = make_float4(acc[0],acc[1],acc[2],acc[3]);
        }
        __syncthreads();
        if (tid < 256) {
            const int c = (int)rank*256 + tid;
            float4 p0 = ((const float4*)redT)[tid];
            float4 p1 = ((const float4*)redT)[256 + tid];
            float4 v;
            v.x = elu_f(p0.x + p1.x + g_act_proj[((b0+0)*64 + t)*512 + c]);
            v.y = elu_f(p0.y + p1.y + g_act_proj[((b0+1)*64 + t)*512 + c]);
            v.z = elu_f(p0.z + p1.z + g_act_proj[((b0+2)*64 + t)*512 + c]);
            v.w = elu_f(p0.w + p1.w + g_act_proj[((b0+3)*64 + t)*512 + c]);
            ((float4*)x1T)[c] = v;
            st_peer_f4(smem_u32(&((float4*)x1T)[c]), peer, v);
        }
        CLUSTER_SYNC();
        // ---- S1a: zr gates + ax; r-threads also form rh = r.*det ---------
        if (tid < 256) {
            // z col zc and ax col ac (full K)
            const int zc = (int)rank*256 + tid;
            float az[4] = {0.f,0.f,0.f,0.f};
            float aa[4] = {0.f,0.f,0.f,0.f};
            #pragma unroll 4
            for (int k = 0; k < 512; k++) {
                float4 x4 = ((const float4*)x1T)[k];
                float4 d4 = ((const float4*)detT)[k];
                float wiz = gru_wi[k*1536 + zc];
                float whz = gru_wh[k*1536 + zc];
                float wia = gru_wi[k*1536 + 1024 + zc];
                az[0] += x4.x*wiz + d4.x*whz;  aa[0] += x4.x*wia;
                az[1] += x4.y*wiz + d4.y*whz;  aa[1] += x4.y*wia;
                az[2] += x4.z*wiz + d4.z*whz;  aa[2] += x4.z*wia;
                az[3] += x4.w*wiz + d4.w*whz;  aa[3] += x4.w*wia;
            }
            float bz = gru_b[zc], ba = gru_b[1024 + zc];
            float4 zv = {sigm_f(az[0]+bz), sigm_f(az[1]+bz), sigm_f(az[2]+bz), sigm_f(az[3]+bz)};
            ((float4*)zT)[zc] = zv;
            float4 av = {aa[0]+ba, aa[1]+ba, aa[2]+ba, aa[3]+ba};
            ((float4*)axT)[zc] = av;
        } else {
            // r col (weight col 512+rank*256+j), then rh
            const int j  = tid - 256;
            const int rc = 512 + (int)rank*256 + j;
            float ar[4] = {0.f,0.f,0.f,0.f};
            #pragma unroll 4
            for (int k = 0; k < 512; k++) {
                float4 x4 = ((const float4*)x1T)[k];
                float4 d4 = ((const float4*)detT)[k];
                float wir = gru_wi[k*1536 + rc];
                float whr = gru_wh[k*1536 + rc];
                ar[0] += x4.x*wir + d4.x*whr;
                ar[1] += x4.y*wir + d4.y*whr;
                ar[2] += x4.z*wir + d4.z*whr;
                ar[3] += x4.w*wir + d4.w*whr;
            }
            float br = gru_b[rc];
            const int dc = (int)rank*256 + j;
            float4 d4 = ((const float4*)detT)[dc];
            float4 rh;
            rh.x = sigm_f(ar[0]+br)*d4.x;
            rh.y = sigm_f(ar[1]+br)*d4.y;
            rh.z = sigm_f(ar[2]+br)*d4.z;
            rh.w = sigm_f(ar[3]+br)*d4.w;
            ((float4*)rhT)[dc] = rh;
            st_peer_f4(smem_u32(&((float4*)rhT)[dc]), peer, rh);
        }
        CLUSTER_SYNC();
        // ---- S1c: ah = rh @ Wh_a (K-split), combine -> det_new ------------
        {
            float acc[4] = {0.f,0.f,0.f,0.f};
            const int kbeg = kh*256;
            #pragma unroll 4
            for (int k = kbeg; k < kbeg+256; k++) {
                float4 h4 = ((const float4*)rhT)[k];
                float w = gru_wh[k*1536 + 1024 + cOwn];
                acc[0] += h4.x*w; acc[1] += h4.y*w;
                acc[2] += h4.z*w; acc[3] += h4.w*w;
            }
            ((float4*)redT)[kh*256 + j256] = make_float4(acc[0],acc[1],acc[2],acc[3]);
        }
        __syncthreads();
        if (tid < 256) {
            const int c = (int)rank*256 + tid;
            float4 p0 = ((const float4*)redT)[tid];
            float4 p1 = ((const float4*)redT)[256 + tid];
            float4 z4 = ((const float4*)zT)[c];
            float4 a4 = ((const float4*)axT)[c];
            float4 d4 = ((const float4*)detT)[c];
            float ah[4] = {p0.x+p1.x, p0.y+p1.y, p0.z+p1.z, p0.w+p1.w};
            float z[4]  = {z4.x, z4.y, z4.z, z4.w};
            float ax[4] = {a4.x, a4.y, a4.z, a4.w};
            float d[4]  = {d4.x, d4.y, d4.z, d4.w};
            float4 dn;
            float* dnp = (float*)&dn;
            #pragma unroll
            for (int r = 0; r < 4; r++) {
                float av = tanhf(ax[r] + ah[r]);
                dnp[r] = (1.f - z[r])*d[r] + z[r]*av;
            }
            ((float4*)detT)[c] = dn;
            st_peer_f4(smem_u32(&((float4*)detT)[c]), peer, dn);
            #pragma unroll
            for (int r = 0; r < 4; r++)
                out[((b0 + r)*64 + t)*OUTW + 128 + c] = dnp[r];
        }
        CLUSTER_SYNC();
        // ---- S2: x3 = elu(obs_proj + det @ post_w1[:512])  (K-split) -----
        {
            float acc[4] = {0.f,0.f,0.f,0.f};
            const int kbeg = kh*256;
            #pragma unroll 4
            for (int k = kbeg; k < kbeg+256; k++) {
                float4 d4 = ((const float4*)detT)[k];
                float w = post_w1[k*512 + cOwn];
                acc[0] += d4.x*w; acc[1] += d4.y*w;
                acc[2] += d4.z*w; acc[3] += d4.w*w;
            }
            ((float4*)redT)[kh*256 + j256] = make_float4(acc[0],acc[1],acc[2],acc[3]);
        }
        __syncthreads();
        if (tid < 256) {
            const int c = (int)rank*256 + tid;
            float4 p0 = ((const float4*)redT)[tid];
            float4 p1 = ((const float4*)redT)[256 + tid];
            float4 v;
            v.x = elu_f(p0.x + p1.x + g_obs_proj[((b0+0)*64 + t)*512 + c]);
            v.y = elu_f(p0.y + p1.y + g_obs_proj[((b0+1)*64 + t)*512 + c]);
            v.z = elu_f(p0.z + p1.z + g_obs_proj[((b0+2)*64 + t)*512 + c]);
            v.w = elu_f(p0.w + p1.w + g_obs_proj[((b0+3)*64 + t)*512 + c]);
            ((float4*)x3T)[c] = v;
            st_peer_f4(smem_u32(&((float4*)x3T)[c]), peer, v);
        }
        CLUSTER_SYNC();
        // ---- S3: q = x3 @ post_w2 + b2 (duplicated both CTAs, K-split) ---
        {
            float acc[4] = {0.f,0.f,0.f,0.f};
            const int kbeg = kh*256;
            #pragma unroll 4
            for (int k = kbeg; k < kbeg+256; k++) {
                float4 x4 = ((const float4*)x3T)[k];
                float w = post_w2[k*256 + j256];
                acc[0] += x4.x*w; acc[1] += x4.y*w;
                acc[2] += x4.z*w; acc[3] += x4.w*w;
            }
            ((float4*)redT)[kh*256 + j256] = make_float4(acc[0],acc[1],acc[2],acc[3]);
        }
        __syncthreads();
        // ---- S3b: stats, posterior sample, write outputs -----------------
        if (tid < 128) {
            const int j = tid;
            float4 m0 = ((const float4*)redT)[j];
            float4 m1 = ((const float4*)redT)[256 + j];
            float4 s0 = ((const float4*)redT)[128 + j];
            float4 s1 = ((const float4*)redT)[384 + j];
            float bm = post_b2[j], bs = post_b2[128 + j];
            float qm[4] = {m0.x+m1.x+bm, m0.y+m1.y+bm, m0.z+m1.z+bm, m0.w+m1.w+bm};
            float qs[4];
            qs[0] = softplus_f(s0.x+s1.x+bs) + 0.1f;
            qs[1] = softplus_f(s0.y+s1.y+bs) + 0.1f;
            qs[2] = softplus_f(s0.z+s1.z+bs) + 0.1f;
            qs[3] = softplus_f(s0.w+s1.w+bs) + 0.1f;
            float4 st;
            float* stp = (float*)&st;
            #pragma unroll
            for (int r = 0; r < 4; r++) {
                float nq = noise_post[((b0 + r)*64 + t)*128 + j];
                stp[r] = qm[r] + qs[r]*nq;
            }
            ((float4*)stochT)[j] = st;
            if (rank == 0) {
                #pragma unroll
                for (int r = 0; r < 4; r++) {
                    int base = ((b0 + r)*64 + t)*OUTW;
                    out[base + j]        = stp[r];
                    out[base + 896 + j]  = qm[r];
                    out[base + 1024 + j] = qs[r];
                }
            }
        }
        __syncthreads();
    }
    CLUSTER_SYNC();
}

// ---------------------------------------------------------------------------
// Deferred prior branch (batched over all B*T rows)
// ---------------------------------------------------------------------------
#define SMEM_PRI (2*32*513*4)

__global__ __launch_bounds__(256) void prior_branch(
    const float* __restrict__ pw2, const float* __restrict__ pb2,
    const float* __restrict__ pw3, const float* __restrict__ pb3,
    float* __restrict__ out)
{
    extern __shared__ __align__(16) float sm2[];
    float* As = sm2;             // [32][513]
    float* Xp = sm2 + 32*513;    // [32][513]

    const int tid = threadIdx.x;
    const int m0  = blockIdx.x * 32;

    for (int i = tid; i < 32*512; i += 256) {
        int r = i >> 9, c = i & 511;
        As[r*513 + c] = out[(m0 + r)*OUTW + 128 + c];
    }
    __syncthreads();

    const int rw = tid >> 6;
    const int nc = tid & 63;

    {
        float acc[8][8];
        #pragma unroll
        for (int i = 0; i < 8; i++)
            #pragma unroll
            for (int j = 0; j < 8; j++) acc[i][j] = 0.f;
        #pragma unroll 2
        for (int k = 0; k < 512; k++) {
            float a[8];
            #pragma unroll
            for (int i = 0; i < 8; i++) a[i] = As[(rw*8 + i)*513 + k];
            float4 w0 = *(const float4*)&pw2[k*512 + nc*8];
            float4 w1 = *(const float4*)&pw2[k*512 + nc*8 + 4];
            float w[8] = {w0.x, w0.y, w0.z, w0.w, w1.x, w1.y, w1.z, w1.w};
            #pragma unroll
            for (int i = 0; i < 8; i++)
                #pragma unroll
                for (int j = 0; j < 8; j++) acc[i][j] += a[i]*w[j];
        }
        #pragma unroll
        for (int i = 0; i < 8; i++)
            #pragma unroll
            for (int j = 0; j < 8; j++)
                Xp[(rw*8 + i)*513 + nc*8 + j] = elu_f(acc[i][j] + pb2[nc*8 + j]);
    }
    __syncthreads();
    {
        float acc[8][4];
        #pragma unroll
        for (int i = 0; i < 8; i++)
            #pragma unroll
            for (int j = 0; j < 4; j++) acc[i][j] = 0.f;
        #pragma unroll 2
        for (int k = 0; k < 512; k++) {
            float a[8];
            #pragma unroll
            for (int i = 0; i < 8; i++) a[i] = Xp[(rw*8 + i)*513 + k];
            float4 w4 = *(const float4*)&pw3[k*256 + nc*4];
            float w[4] = {w4.x, w4.y, w4.z, w4.w};
            #pragma unroll
            for (int i = 0; i < 8; i++)
                #pragma unroll
                for (int j = 0; j < 4; j++) acc[i][j] += a[i]*w[j];
        }
        #pragma unroll
        for (int i = 0; i < 8; i++) {
            int m = m0 + rw*8 + i;
            #pragma unroll
            for (int j = 0; j < 4; j++) {
                int c = nc*4 + j;
                float v = acc[i][j] + pb3[c];
                if (c < 128) out[m*OUTW + 640 + c] = v;
                else         out[m*OUTW + 768 + (c - 128)] = softplus_f(v) + 0.1f;
            }
        }
    }
}

// ---------------------------------------------------------------------------
extern "C" void kernel_launch(void* const* d_in, const int* in_sizes, int n_in,
                              void* d_out, int out_size)
{
    const float* observations = (const float*)d_in[0];
    const float* actions      = (const float*)d_in[1];
    // d_in[2] = noise_prior: unused (prior sample is dead in the reference)
    const float* noise_post   = (const float*)d_in[3];
    const float* prior_w1     = (const float*)d_in[4];
    const float* prior_b1     = (const float*)d_in[5];
    const float* gru_wi       = (const float*)d_in[6];
    const float* gru_wh       = (const float*)d_in[7];
    const float* gru_b        = (const float*)d_in[8];
    const float* prior_w2     = (const float*)d_in[9];
    const float* prior_b2     = (const float*)d_in[10];
    const float* prior_w3     = (const float*)d_in[11];
    const float* prior_b3     = (const float*)d_in[12];
    const float* post_w1      = (const float*)d_in[13];
    const float* post_b1      = (const float*)d_in[14];
    const float* post_w2      = (const float*)d_in[15];
    const float* post_b2      = (const float*)d_in[16];
    float* out = (float*)d_out;

    float *actp, *obsp;
    cudaGetSymbolAddress((void**)&actp, g_act_proj);
    cudaGetSymbolAddress((void**)&obsp, g_obs_proj);

    cudaFuncSetAttribute(rssm_recur, cudaFuncAttributeMaxDynamicSharedMemorySize, SMEM_REC);
    cudaFuncSetAttribute(prior_branch, cudaFuncAttributeMaxDynamicSharedMemorySize, SMEM_PRI);

    // Batched precompute (prerequisites of the scan)
    proj_gemm<<<dim3(8, BT/64), 256>>>(actions, prior_w1, prior_b1, actp, ACTD);
    proj_gemm<<<dim3(8, BT/64), 256>>>(observations, post_w1 + 512*512, post_b1, obsp, OBSD);
    // Sequential recurrence: 64 clusters x 2 CTAs x 512 threads
    rssm_recur<<<128, 512, SMEM_REC>>>(prior_w1, gru_wi, gru_wh, gru_b,
                                       post_w1, post_w2, post_b2, noise_post, out);
    // Deferred prior head, batched over all B*T rows
    prior_branch<<<BT/32, 256, SMEM_PRI>>>(prior_w2, prior_b2, prior_w3, prior_b3, out);
}

// round 5
// speedup vs baseline: 3.3102x; 1.5071x over previous
#include <cuda_runtime.h>
#include <math.h>
#include <stdint.h>

#define B_    256
#define T_    64
#define STOCH 128
#define DETD  512
#define HIDD  512
#define OBSD  1024
#define ACTD  32
#define BT    (B_*T_)
#define OUTW  1152

// Scratch (device globals). TRANSPOSED layout: [t][c][b]  (b fastest)
__device__ float g_act_proj[T_*DETD*B_];
__device__ float g_obs_proj[T_*HIDD*B_];

__device__ __forceinline__ float elu_f(float x)      { return x > 0.f ? x : (__expf(x) - 1.f); }
__device__ __forceinline__ float sigm_f(float x)     { return 1.f/(1.f+__expf(-x)); }
__device__ __forceinline__ float softplus_f(float x) { return fmaxf(x,0.f) + log1pf(__expf(-fabsf(x))); }

__device__ __forceinline__ uint32_t smem_u32(const void* p) {
    uint32_t a;
    asm("{ .reg .u64 t; cvta.to.shared.u64 t, %1; cvt.u32.u64 %0, t; }" : "=r"(a) : "l"(p));
    return a;
}
// packed fp32x2 FMA (FFMA2): d.lo += a.lo*b.lo ; d.hi += a.hi*b.hi
__device__ __forceinline__ void fma2(unsigned long long& d, unsigned long long a, unsigned long long b) {
    asm("fma.rn.f32x2 %0, %1, %2, %0;" : "+l"(d) : "l"(a), "l"(b));
}
__device__ __forceinline__ unsigned long long pack2(float w) {
    unsigned long long r;
    unsigned int u = __float_as_uint(w);
    asm("mov.b64 %0, {%1, %1};" : "=l"(r) : "r"(u));
    return r;
}
// store 8 floats (lo,hi) into the 3 peer CTAs' SMEM at the same offset
__device__ __forceinline__ void bcast3(const float* dst, float4 lo, float4 hi, uint32_t rank) {
    uint32_t la = smem_u32(dst);
    #pragma unroll
    for (uint32_t pr = 0; pr < 4; pr++) {
        if (pr == rank) continue;
        uint32_t ra;
        asm("mapa.shared::cluster.u32 %0, %1, %2;" : "=r"(ra) : "r"(la), "r"(pr));
        asm volatile("st.shared::cluster.v4.f32 [%0], {%1,%2,%3,%4};"
                     :: "r"(ra), "f"(lo.x), "f"(lo.y), "f"(lo.z), "f"(lo.w) : "memory");
        asm volatile("st.shared::cluster.v4.f32 [%0+16], {%1,%2,%3,%4};"
                     :: "r"(ra), "f"(hi.x), "f"(hi.y), "f"(hi.z), "f"(hi.w) : "memory");
    }
}
#define CLUSTER_SYNC() do { \
    asm volatile("barrier.cluster.arrive.aligned;" ::: "memory"); \
    asm volatile("barrier.cluster.wait.aligned;"   ::: "memory"); \
} while (0)

// ---------------------------------------------------------------------------
// Batched projection GEMM with TRANSPOSED output: C[(t*512+n)*256 + b],
// where input row m = b*64+t.
// ---------------------------------------------------------------------------
__global__ __launch_bounds__(256) void proj_gemm(
    const float* __restrict__ A, const float* __restrict__ W,
    const float* __restrict__ bias, float* __restrict__ C, int K)
{
    __shared__ __align__(16) float Ast[16][68];
    __shared__ __align__(16) float Bs[16][64];

    const int tid = threadIdx.x;
    const int m0 = blockIdx.y * 64;
    const int n0 = blockIdx.x * 64;
    const int tx = tid & 15, ty = tid >> 4;

    const int arow = tid >> 2;
    const int avec = (tid & 3) * 4;
    const int bk   = tid >> 4;
    const int bn   = (tid & 15) * 4;

    float acc[4][4];
    #pragma unroll
    for (int i = 0; i < 4; i++)
        #pragma unroll
        for (int j = 0; j < 4; j++) acc[i][j] = 0.f;

    for (int k0 = 0; k0 < K; k0 += 16) {
        float4 av = *(const float4*)&A[(m0 + arow) * K + k0 + avec];
        Ast[avec+0][arow] = av.x;
        Ast[avec+1][arow] = av.y;
        Ast[avec+2][arow] = av.z;
        Ast[avec+3][arow] = av.w;
        float4 bv = *(const float4*)&W[(k0 + bk) * 512 + n0 + bn];
        *(float4*)&Bs[bk][bn] = bv;
        __syncthreads();
        #pragma unroll
        for (int kk = 0; kk < 16; kk++) {
            float4 a4 = *(const float4*)&Ast[kk][ty*4];
            float4 b4 = *(const float4*)&Bs[kk][tx*4];
            float a[4] = {a4.x, a4.y, a4.z, a4.w};
            float b[4] = {b4.x, b4.y, b4.z, b4.w};
            #pragma unroll
            for (int i = 0; i < 4; i++)
                #pragma unroll
                for (int j = 0; j < 4; j++) acc[i][j] += a[i]*b[j];
        }
        __syncthreads();
    }

    #pragma unroll
    for (int i = 0; i < 4; i++) {
        int m = m0 + ty*4 + i;
        int bb = m >> 6, tt = m & 63;
        #pragma unroll
        for (int j = 0; j < 4; j++) {
            int n = n0 + tx*4 + j;
            C[(tt*512 + n)*256 + bb] = acc[i][j] + bias[n];
        }
    }
}

// ---------------------------------------------------------------------------
// Persistent recurrence: 128 CTAs = 32 clusters of 4. Each cluster owns 8
// batch rows; each CTA computes 1/4 of the output columns and exchanges
// activation quarters via DSMEM. Inner GEMMs use packed fma.rn.f32x2 over
// row-pairs. Activations stored [col][8 rows] (32B per col).
// GRU note: reference's `r * h @ Wh` == (r*h) @ Wh (left-assoc).
// SMEM floats: stochT 1024 | detT 4096 | x1T 4096 | x3T 4096 | zT 4096 |
//              rhT 4096 | redT 4096  = 25600 floats = 102400 B
// ---------------------------------------------------------------------------
#define SMEM_REC (25600*4)

__global__ __launch_bounds__(512, 1) __cluster_dims__(4, 1, 1)
void rssm_recur(
    const float* __restrict__ prior_w1,   // 160x512
    const float* __restrict__ gru_wi,     // 512x1536
    const float* __restrict__ gru_wh,     // 512x1536
    const float* __restrict__ gru_b,      // 1536
    const float* __restrict__ post_w1,    // 1536x512 (rows 0..511 = det part)
    const float* __restrict__ post_w2,    // 512x256
    const float* __restrict__ post_b2,    // 256
    const float* __restrict__ noise_post, // B,T,128
    float* __restrict__ out)              // B,T,1152
{
    extern __shared__ __align__(16) float sm[];
    float* stochT = sm;            // [128][8]
    float* detT   = sm + 1024;     // [512][8]
    float* x1T    = sm + 5120;     // [512][8]
    float* x3T    = sm + 9216;     // [512][8]
    float* zT     = sm + 13312;    // [512][8] (only owned 128 cols used)
    float* rhT    = sm + 17408;    // [512][8]
    float* redT   = sm + 21504;    // [8 slots][ .. ][8] = 4096 floats max

    const int tid = threadIdx.x;
    uint32_t rank;
    asm("mov.u32 %0, %%cluster_ctarank;" : "=r"(rank));
    const int b0 = (blockIdx.x >> 2) * 8;
    const float* W1s = prior_w1 + 32*512;

    for (int i = tid; i < 1024; i += 512) stochT[i] = 0.f;
    for (int i = tid; i < 4096; i += 512) detT[i]   = 0.f;
    __syncthreads();
    CLUSTER_SYNC();

    for (int t = 0; t < T_; t++) {
        // ======== S0: x1 = elu(act_proj + stoch @ W1s), K=128, ks4 ========
        {
            const int col = tid & 127;
            const int ks  = tid >> 7;              // 0..3, 32 K each
            const int gc  = (int)rank*128 + col;
            unsigned long long a0=0,a1=0,a2=0,a3=0;
            #pragma unroll 8
            for (int k = ks*32; k < ks*32+32; k++) {
                const unsigned long long* ap = (const unsigned long long*)(stochT + k*8);
                unsigned long long wp = pack2(W1s[k*512 + gc]);
                fma2(a0, ap[0], wp); fma2(a1, ap[1], wp);
                fma2(a2, ap[2], wp); fma2(a3, ap[3], wp);
            }
            unsigned long long* rd = (unsigned long long*)(redT + (ks*128 + col)*8);
            rd[0]=a0; rd[1]=a1; rd[2]=a2; rd[3]=a3;
        }
        __syncthreads();
        if (tid < 128) {
            const int gc = (int)rank*128 + tid;
            float4 lo = make_float4(0,0,0,0), hi = make_float4(0,0,0,0);
            #pragma unroll
            for (int s = 0; s < 4; s++) {
                float4 l = *(const float4*)&redT[(s*128 + tid)*8];
                float4 h = *(const float4*)&redT[(s*128 + tid)*8 + 4];
                lo.x+=l.x; lo.y+=l.y; lo.z+=l.z; lo.w+=l.w;
                hi.x+=h.x; hi.y+=h.y; hi.z+=h.z; hi.w+=h.w;
            }
            const float* ap = &g_act_proj[(t*512 + gc)*256 + b0];
            float4 p0 = *(const float4*)ap, p1 = *(const float4*)(ap+4);
            lo.x = elu_f(lo.x+p0.x); lo.y = elu_f(lo.y+p0.y);
            lo.z = elu_f(lo.z+p0.z); lo.w = elu_f(lo.w+p0.w);
            hi.x = elu_f(hi.x+p1.x); hi.y = elu_f(hi.y+p1.y);
            hi.z = elu_f(hi.z+p1.z); hi.w = elu_f(hi.w+p1.w);
            *(float4*)&x1T[gc*8]     = lo;
            *(float4*)&x1T[gc*8 + 4] = hi;
            bcast3(&x1T[gc*8], lo, hi, rank);
        }
        CLUSTER_SYNC();
        // ======== S1a: z & r gates, full K=512 split 2, per gate ==========
        {
            const int group = tid >> 8;            // 0=z, 1=r
            const int sub   = tid & 255;
            const int col   = sub & 127;
            const int ks    = sub >> 7;            // 0/1, 256 K each
            const int wcol  = group ? (512 + (int)rank*128 + col)
                                    : ((int)rank*128 + col);
            unsigned long long a0=0,a1=0,a2=0,a3=0;
            #pragma unroll 4
            for (int k = ks*256; k < ks*256+256; k++) {
                const unsigned long long* xa = (const unsigned long long*)(x1T + k*8);
                const unsigned long long* da = (const unsigned long long*)(detT + k*8);
                unsigned long long wi = pack2(gru_wi[k*1536 + wcol]);
                unsigned long long wh = pack2(gru_wh[k*1536 + wcol]);
                fma2(a0, xa[0], wi); fma2(a1, xa[1], wi);
                fma2(a2, xa[2], wi); fma2(a3, xa[3], wi);
                fma2(a0, da[0], wh); fma2(a1, da[1], wh);
                fma2(a2, da[2], wh); fma2(a3, da[3], wh);
            }
            unsigned long long* rd = (unsigned long long*)(redT + ((group*2+ks)*128 + col)*8);
            rd[0]=a0; rd[1]=a1; rd[2]=a2; rd[3]=a3;
        }
        __syncthreads();
        if (tid < 256) {
            const int half = tid >> 7;             // 0=z, 1=r
            const int c    = tid & 127;
            const int gc   = (int)rank*128 + c;
            float4 lo = make_float4(0,0,0,0), hi = make_float4(0,0,0,0);
            #pragma unroll
            for (int s = half*2; s < half*2+2; s++) {
                float4 l = *(const float4*)&redT[(s*128 + c)*8];
                float4 h = *(const float4*)&redT[(s*128 + c)*8 + 4];
                lo.x+=l.x; lo.y+=l.y; lo.z+=l.z; lo.w+=l.w;
                hi.x+=h.x; hi.y+=h.y; hi.z+=h.z; hi.w+=h.w;
            }
            if (half == 0) {
                float b = gru_b[gc];
                lo.x=sigm_f(lo.x+b); lo.y=sigm_f(lo.y+b); lo.z=sigm_f(lo.z+b); lo.w=sigm_f(lo.w+b);
                hi.x=sigm_f(hi.x+b); hi.y=sigm_f(hi.y+b); hi.z=sigm_f(hi.z+b); hi.w=sigm_f(hi.w+b);
                *(float4*)&zT[gc*8]     = lo;
                *(float4*)&zT[gc*8 + 4] = hi;
            } else {
                float b = gru_b[512 + gc];
                float4 dlo = *(const float4*)&detT[gc*8];
                float4 dhi = *(const float4*)&detT[gc*8 + 4];
                lo.x=sigm_f(lo.x+b)*dlo.x; lo.y=sigm_f(lo.y+b)*dlo.y;
                lo.z=sigm_f(lo.z+b)*dlo.z; lo.w=sigm_f(lo.w+b)*dlo.w;
                hi.x=sigm_f(hi.x+b)*dhi.x; hi.y=sigm_f(hi.y+b)*dhi.y;
                hi.z=sigm_f(hi.z+b)*dhi.z; hi.w=sigm_f(hi.w+b)*dhi.w;
                *(float4*)&rhT[gc*8]     = lo;
                *(float4*)&rhT[gc*8 + 4] = hi;
                bcast3(&rhT[gc*8], lo, hi, rank);
            }
        }
        CLUSTER_SYNC();
        // ======== S1c: ah = rh@Wh_a, ax = x1@Wi_a; det update =============
        {
            const int group = tid >> 8;            // 0=ah, 1=ax
            const int sub   = tid & 255;
            const int col   = sub & 127;
            const int ks    = sub >> 7;            // 256 K each
            const int wcol  = 1024 + (int)rank*128 + col;
            const float* W   = group ? gru_wi : gru_wh;
            const float* act = group ? x1T : rhT;
            unsigned long long a0=0,a1=0,a2=0,a3=0;
            #pragma unroll 8
            for (int k = ks*256; k < ks*256+256; k++) {
                const unsigned long long* ap = (const unsigned long long*)(act + k*8);
                unsigned long long wp = pack2(W[k*1536 + wcol]);
                fma2(a0, ap[0], wp); fma2(a1, ap[1], wp);
                fma2(a2, ap[2], wp); fma2(a3, ap[3], wp);
            }
            unsigned long long* rd = (unsigned long long*)(redT + ((group*2+ks)*128 + col)*8);
            rd[0]=a0; rd[1]=a1; rd[2]=a2; rd[3]=a3;
        }
        __syncthreads();
        if (tid < 128) {
            const int gc = (int)rank*128 + tid;
            float ah[8], ax[8];
            {
                float4 l0 = *(const float4*)&redT[(0*128+tid)*8];
                float4 h0 = *(const float4*)&redT[(0*128+tid)*8+4];
                float4 l1 = *(const float4*)&redT[(1*128+tid)*8];
                float4 h1 = *(const float4*)&redT[(1*128+tid)*8+4];
                ah[0]=l0.x+l1.x; ah[1]=l0.y+l1.y; ah[2]=l0.z+l1.z; ah[3]=l0.w+l1.w;
                ah[4]=h0.x+h1.x; ah[5]=h0.y+h1.y; ah[6]=h0.z+h1.z; ah[7]=h0.w+h1.w;
                float4 l2 = *(const float4*)&redT[(2*128+tid)*8];
                float4 h2 = *(const float4*)&redT[(2*128+tid)*8+4];
                float4 l3 = *(const float4*)&redT[(3*128+tid)*8];
                float4 h3 = *(const float4*)&redT[(3*128+tid)*8+4];
                float b = gru_b[1024 + gc];
                ax[0]=l2.x+l3.x+b; ax[1]=l2.y+l3.y+b; ax[2]=l2.z+l3.z+b; ax[3]=l2.w+l3.w+b;
                ax[4]=h2.x+h3.x+b; ax[5]=h2.y+h3.y+b; ax[6]=h2.z+h3.z+b; ax[7]=h2.w+h3.w+b;
            }
            float z[8], d[8], dn[8];
            *(float4*)&z[0] = *(const float4*)&zT[gc*8];
            *(float4*)&z[4] = *(const float4*)&zT[gc*8+4];
            *(float4*)&d[0] = *(const float4*)&detT[gc*8];
            *(float4*)&d[4] = *(const float4*)&detT[gc*8+4];
            #pragma unroll
            for (int r = 0; r < 8; r++) {
                float av = tanhf(ax[r] + ah[r]);
                dn[r] = (1.f - z[r])*d[r] + z[r]*av;
            }
            float4 lo = make_float4(dn[0],dn[1],dn[2],dn[3]);
            float4 hi = make_float4(dn[4],dn[5],dn[6],dn[7]);
            *(float4*)&detT[gc*8]   = lo;
            *(float4*)&detT[gc*8+4] = hi;
            bcast3(&detT[gc*8], lo, hi, rank);
            #pragma unroll
            for (int r = 0; r < 8; r++)
                out[((b0 + r)*64 + t)*OUTW + 128 + gc] = dn[r];
        }
        CLUSTER_SYNC();
        // ======== S2: x3 = elu(obs_proj + det @ post_w1[:512]), ks4 =======
        {
            const int col = tid & 127;
            const int ks  = tid >> 7;              // 128 K each
            const int gc  = (int)rank*128 + col;
            unsigned long long a0=0,a1=0,a2=0,a3=0;
            #pragma unroll 8
            for (int k = ks*128; k < ks*128+128; k++) {
                const unsigned long long* ap = (const unsigned long long*)(detT + k*8);
                unsigned long long wp = pack2(post_w1[k*512 + gc]);
                fma2(a0, ap[0], wp); fma2(a1, ap[1], wp);
                fma2(a2, ap[2], wp); fma2(a3, ap[3], wp);
            }
            unsigned long long* rd = (unsigned long long*)(redT + (ks*128 + col)*8);
            rd[0]=a0; rd[1]=a1; rd[2]=a2; rd[3]=a3;
        }
        __syncthreads();
        if (tid < 128) {
            const int gc = (int)rank*128 + tid;
            float4 lo = make_float4(0,0,0,0), hi = make_float4(0,0,0,0);
            #pragma unroll
            for (int s = 0; s < 4; s++) {
                float4 l = *(const float4*)&redT[(s*128 + tid)*8];
                float4 h = *(const float4*)&redT[(s*128 + tid)*8 + 4];
                lo.x+=l.x; lo.y+=l.y; lo.z+=l.z; lo.w+=l.w;
                hi.x+=h.x; hi.y+=h.y; hi.z+=h.z; hi.w+=h.w;
            }
            const float* op = &g_obs_proj[(t*512 + gc)*256 + b0];
            float4 p0 = *(const float4*)op, p1 = *(const float4*)(op+4);
            lo.x = elu_f(lo.x+p0.x); lo.y = elu_f(lo.y+p0.y);
            lo.z = elu_f(lo.z+p0.z); lo.w = elu_f(lo.w+p0.w);
            hi.x = elu_f(hi.x+p1.x); hi.y = elu_f(hi.y+p1.y);
            hi.z = elu_f(hi.z+p1.z); hi.w = elu_f(hi.w+p1.w);
            *(float4*)&x3T[gc*8]     = lo;
            *(float4*)&x3T[gc*8 + 4] = hi;
            bcast3(&x3T[gc*8], lo, hi, rank);
        }
        CLUSTER_SYNC();
        // ======== S3: q = x3 @ post_w2 + b2 (64 q-cols/CTA, ks8) ==========
        {
            const int l  = tid & 63;
            const int ks = tid >> 6;               // 0..7, 64 K each
            const int qcol = (l < 32) ? ((int)rank*32 + l)
                                      : (128 + (int)rank*32 + (l - 32));
            unsigned long long a0=0,a1=0,a2=0,a3=0;
            #pragma unroll 8
            for (int k = ks*64; k < ks*64+64; k++) {
                const unsigned long long* ap = (const unsigned long long*)(x3T + k*8);
                unsigned long long wp = pack2(post_w2[k*256 + qcol]);
                fma2(a0, ap[0], wp); fma2(a1, ap[1], wp);
                fma2(a2, ap[2], wp); fma2(a3, ap[3], wp);
            }
            unsigned long long* rd = (unsigned long long*)(redT + (ks*64 + l)*8);
            rd[0]=a0; rd[1]=a1; rd[2]=a2; rd[3]=a3;
        }
        __syncthreads();
        if (tid < 32) {
            const int j = (int)rank*32 + tid;
            float qm[8] = {0,0,0,0,0,0,0,0}, qs[8] = {0,0,0,0,0,0,0,0};
            #pragma unroll
            for (int s = 0; s < 8; s++) {
                const float* pm = &redT[(s*64 + tid)*8];
                const float* ps = &redT[(s*64 + 32 + tid)*8];
                #pragma unroll
                for (int r = 0; r < 8; r++) { qm[r] += pm[r]; qs[r] += ps[r]; }
            }
            float bm = post_b2[j], bs = post_b2[128 + j];
            float st[8];
            #pragma unroll
            for (int r = 0; r < 8; r++) {
                qm[r] += bm;
                qs[r] = softplus_f(qs[r] + bs) + 0.1f;
                float nq = noise_post[((b0 + r)*64 + t)*128 + j];
                st[r] = qm[r] + qs[r]*nq;
            }
            float4 lo = make_float4(st[0],st[1],st[2],st[3]);
            float4 hi = make_float4(st[4],st[5],st[6],st[7]);
            *(float4*)&stochT[j*8]   = lo;
            *(float4*)&stochT[j*8+4] = hi;
            bcast3(&stochT[j*8], lo, hi, rank);
            #pragma unroll
            for (int r = 0; r < 8; r++) {
                int base = ((b0 + r)*64 + t)*OUTW;
                out[base + j]        = st[r];
                out[base + 896 + j]  = qm[r];
                out[base + 1024 + j] = qs[r];
            }
        }
        CLUSTER_SYNC();
    }
}

// ---------------------------------------------------------------------------
// Deferred prior branch (batched over all B*T rows)
// ---------------------------------------------------------------------------
#define SMEM_PRI (2*32*513*4)

__global__ __launch_bounds__(256) void prior_branch(
    const float* __restrict__ pw2, const float* __restrict__ pb2,
    const float* __restrict__ pw3, const float* __restrict__ pb3,
    float* __restrict__ out)
{
    extern __shared__ __align__(16) float sm2[];
    float* As = sm2;             // [32][513]
    float* Xp = sm2 + 32*513;    // [32][513]

    const int tid = threadIdx.x;
    const int m0  = blockIdx.x * 32;

    for (int i = tid; i < 32*512; i += 256) {
        int r = i >> 9, c = i & 511;
        As[r*513 + c] = out[(m0 + r)*OUTW + 128 + c];
    }
    __syncthreads();

    const int rw = tid >> 6;
    const int nc = tid & 63;

    {
        float acc[8][8];
        #pragma unroll
        for (int i = 0; i < 8; i++)
            #pragma unroll
            for (int j = 0; j < 8; j++) acc[i][j] = 0.f;
        #pragma unroll 2
        for (int k = 0; k < 512; k++) {
            float a[8];
            #pragma unroll
            for (int i = 0; i < 8; i++) a[i] = As[(rw*8 + i)*513 + k];
            float4 w0 = *(const float4*)&pw2[k*512 + nc*8];
            float4 w1 = *(const float4*)&pw2[k*512 + nc*8 + 4];
            float w[8] = {w0.x, w0.y, w0.z, w0.w, w1.x, w1.y, w1.z, w1.w};
            #pragma unroll
            for (int i = 0; i < 8; i++)
                #pragma unroll
                for (int j = 0; j < 8; j++) acc[i][j] += a[i]*w[j];
        }
        #pragma unroll
        for (int i = 0; i < 8; i++)
            #pragma unroll
            for (int j = 0; j < 8; j++)
                Xp[(rw*8 + i)*513 + nc*8 + j] = elu_f(acc[i][j] + pb2[nc*8 + j]);
    }
    __syncthreads();
    {
        float acc[8][4];
        #pragma unroll
        for (int i = 0; i < 8; i++)
            #pragma unroll
            for (int j = 0; j < 4; j++) acc[i][j] = 0.f;
        #pragma unroll 2
        for (int k = 0; k < 512; k++) {
            float a[8];
            #pragma unroll
            for (int i = 0; i < 8; i++) a[i] = Xp[(rw*8 + i)*513 + k];
            float4 w4 = *(const float4*)&pw3[k*256 + nc*4];
            float w[4] = {w4.x, w4.y, w4.z, w4.w};
            #pragma unroll
            for (int i = 0; i < 8; i++)
                #pragma unroll
                for (int j = 0; j < 4; j++) acc[i][j] += a[i]*w[j];
        }
        #pragma unroll
        for (int i = 0; i < 8; i++) {
            int m = m0 + rw*8 + i;
            #pragma unroll
            for (int j = 0; j < 4; j++) {
                int c = nc*4 + j;
                float v = acc[i][j] + pb3[c];
                if (c < 128) out[m*OUTW + 640 + c] = v;
                else         out[m*OUTW + 768 + (c - 128)] = softplus_f(v) + 0.1f;
            }
        }
    }
}

// ---------------------------------------------------------------------------
extern "C" void kernel_launch(void* const* d_in, const int* in_sizes, int n_in,
                              void* d_out, int out_size)
{
    const float* observations = (const float*)d_in[0];
    const float* actions      = (const float*)d_in[1];
    // d_in[2] = noise_prior: unused (prior sample is dead in the reference)
    const float* noise_post   = (const float*)d_in[3];
    const float* prior_w1     = (const float*)d_in[4];
    const float* prior_b1     = (const float*)d_in[5];
    const float* gru_wi       = (const float*)d_in[6];
    const float* gru_wh       = (const float*)d_in[7];
    const float* gru_b        = (const float*)d_in[8];
    const float* prior_w2     = (const float*)d_in[9];
    const float* prior_b2     = (const float*)d_in[10];
    const float* prior_w3     = (const float*)d_in[11];
    const float* prior_b3     = (const float*)d_in[12];
    const float* post_w1      = (const float*)d_in[13];
    const float* post_b1      = (const float*)d_in[14];
    const float* post_w2      = (const float*)d_in[15];
    const float* post_b2      = (const float*)d_in[16];
    float* out = (float*)d_out;

    float *actp, *obsp;
    cudaGetSymbolAddress((void**)&actp, g_act_proj);
    cudaGetSymbolAddress((void**)&obsp, g_obs_proj);

    cudaFuncSetAttribute(rssm_recur, cudaFuncAttributeMaxDynamicSharedMemorySize, SMEM_REC);
    cudaFuncSetAttribute(prior_branch, cudaFuncAttributeMaxDynamicSharedMemorySize, SMEM_PRI);

    // Batched precompute (prerequisites of the scan), transposed outputs
    proj_gemm<<<dim3(8, BT/64), 256>>>(actions, prior_w1, prior_b1, actp, ACTD);
    proj_gemm<<<dim3(8, BT/64), 256>>>(observations, post_w1 + 512*512, post_b1, obsp, OBSD);
    // Sequential recurrence: 32 clusters x 4 CTAs x 512 threads
    rssm_recur<<<128, 512, SMEM_REC>>>(prior_w1, gru_wi, gru_wh, gru_b,
                                       post_w1, post_w2, post_b2, noise_post, out);
    // Deferred prior head, batched over all B*T rows
    prior_branch<<<BT/32, 256, SMEM_PRI>>>(prior_w2, prior_b2, prior_w3, prior_b3, out);
}

// round 6
// speedup vs baseline: 4.8337x; 1.4602x over previous
#include <cuda_runtime.h>
#include <math.h>
#include <stdint.h>

#define B_    256
#define T_    64
#define STOCH 128
#define DETD  512
#define HIDD  512
#define OBSD  1024
#define ACTD  32
#define BT    (B_*T_)
#define OUTW  1152

typedef unsigned long long u64;

// Scratch (device globals). TRANSPOSED layout: [t][c][b]  (b fastest)
__device__ float g_act_proj[T_*DETD*B_];
__device__ float g_obs_proj[T_*HIDD*B_];
__device__ float g_dummy[32];

__device__ __forceinline__ float elu_f(float x)      { return x > 0.f ? x : (__expf(x) - 1.f); }
__device__ __forceinline__ float sigm_f(float x)     { return 1.f/(1.f+__expf(-x)); }
__device__ __forceinline__ float softplus_f(float x) { return fmaxf(x,0.f) + log1pf(__expf(-fabsf(x))); }

__device__ __forceinline__ uint32_t smem_u32(const void* p) {
    uint32_t a;
    asm("{ .reg .u64 t; cvta.to.shared.u64 t, %1; cvt.u32.u64 %0, t; }" : "=r"(a) : "l"(p));
    return a;
}
// packed fp32x2 FMA: d.lo += a.lo*b.lo ; d.hi += a.hi*b.hi
__device__ __forceinline__ void fma2(u64& d, u64 a, u64 b) {
    asm("fma.rn.f32x2 %0, %1, %2, %0;" : "+l"(d) : "l"(a), "l"(b));
}
__device__ __forceinline__ u64 pack2(float w) {
    u64 r; unsigned int u = __float_as_uint(w);
    asm("mov.b64 %0, {%1, %1};" : "=l"(r) : "r"(u));
    return r;
}
// 4 cols x 4 row-pairs MAC block: acc[c][rp] += act[rp] * w4[c]
__device__ __forceinline__ void mac16(u64 (&acc)[4][4], const float* actcol, float4 w4) {
    const u64* ap = (const u64*)actcol;
    u64 a0 = ap[0], a1 = ap[1], a2 = ap[2], a3 = ap[3];
    u64 w;
    w = pack2(w4.x); fma2(acc[0][0],a0,w); fma2(acc[0][1],a1,w); fma2(acc[0][2],a2,w); fma2(acc[0][3],a3,w);
    w = pack2(w4.y); fma2(acc[1][0],a0,w); fma2(acc[1][1],a1,w); fma2(acc[1][2],a2,w); fma2(acc[1][3],a3,w);
    w = pack2(w4.z); fma2(acc[2][0],a0,w); fma2(acc[2][1],a1,w); fma2(acc[2][2],a2,w); fma2(acc[2][3],a3,w);
    w = pack2(w4.w); fma2(acc[3][0],a0,w); fma2(acc[3][1],a1,w); fma2(acc[3][2],a2,w); fma2(acc[3][3],a3,w);
}
// redT slot stride = 34 floats (136B) -> u64 stores hit distinct dual-banks
#define RSLOT 34
__device__ __forceinline__ void storePartial(float* redT, int slot, u64 (&acc)[4][4]) {
    u64* rd = (u64*)(redT + slot*RSLOT);
    #pragma unroll
    for (int c = 0; c < 4; c++)
        #pragma unroll
        for (int rp = 0; rp < 4; rp++) rd[c*4 + rp] = acc[c][rp];
}
__device__ __forceinline__ void addP(float s[8], const float* redT, int slot, int c4) {
    const float2* p = (const float2*)(redT + slot*RSLOT + c4*8);
    #pragma unroll
    for (int i = 0; i < 4; i++) { float2 v = p[i]; s[2*i] += v.x; s[2*i+1] += v.y; }
}
// store 8 floats into the 3 peer CTAs' SMEM at the same offset
__device__ __forceinline__ void bcast3(const float* dst, float4 lo, float4 hi, uint32_t rank) {
    uint32_t la = smem_u32(dst);
    #pragma unroll
    for (uint32_t pr = 0; pr < 4; pr++) {
        if (pr == rank) continue;
        uint32_t ra;
        asm("mapa.shared::cluster.u32 %0, %1, %2;" : "=r"(ra) : "r"(la), "r"(pr));
        asm volatile("st.shared::cluster.v4.f32 [%0], {%1,%2,%3,%4};"
                     :: "r"(ra), "f"(lo.x), "f"(lo.y), "f"(lo.z), "f"(lo.w) : "memory");
        asm volatile("st.shared::cluster.v4.f32 [%0+16], {%1,%2,%3,%4};"
                     :: "r"(ra), "f"(hi.x), "f"(hi.y), "f"(hi.z), "f"(hi.w) : "memory");
    }
}
#define CLUSTER_SYNC() do { \
    asm volatile("barrier.cluster.arrive.aligned;" ::: "memory"); \
    asm volatile("barrier.cluster.wait.aligned;"   ::: "memory"); \
} while (0)

__global__ void ncu_align_dummy() { g_dummy[threadIdx.x & 31] = (float)threadIdx.x; }

// ---------------------------------------------------------------------------
// Batched projection GEMM with TRANSPOSED output: C[(t*512+n)*256 + b]
// ---------------------------------------------------------------------------
__global__ __launch_bounds__(256) void proj_gemm(
    const float* __restrict__ A, const float* __restrict__ W,
    const float* __restrict__ bias, float* __restrict__ C, int K)
{
    __shared__ __align__(16) float Ast[16][68];
    __shared__ __align__(16) float Bs[16][64];

    const int tid = threadIdx.x;
    const int m0 = blockIdx.y * 64;
    const int n0 = blockIdx.x * 64;
    const int tx = tid & 15, ty = tid >> 4;

    const int arow = tid >> 2;
    const int avec = (tid & 3) * 4;
    const int bk   = tid >> 4;
    const int bn   = (tid & 15) * 4;

    float acc[4][4];
    #pragma unroll
    for (int i = 0; i < 4; i++)
        #pragma unroll
        for (int j = 0; j < 4; j++) acc[i][j] = 0.f;

    for (int k0 = 0; k0 < K; k0 += 16) {
        float4 av = *(const float4*)&A[(m0 + arow) * K + k0 + avec];
        Ast[avec+0][arow] = av.x;
        Ast[avec+1][arow] = av.y;
        Ast[avec+2][arow] = av.z;
        Ast[avec+3][arow] = av.w;
        float4 bv = *(const float4*)&W[(k0 + bk) * 512 + n0 + bn];
        *(float4*)&Bs[bk][bn] = bv;
        __syncthreads();
        #pragma unroll
        for (int kk = 0; kk < 16; kk++) {
            float4 a4 = *(const float4*)&Ast[kk][ty*4];
            float4 b4 = *(const float4*)&Bs[kk][tx*4];
            float a[4] = {a4.x, a4.y, a4.z, a4.w};
            float b[4] = {b4.x, b4.y, b4.z, b4.w};
            #pragma unroll
            for (int i = 0; i < 4; i++)
                #pragma unroll
                for (int j = 0; j < 4; j++) acc[i][j] += a[i]*b[j];
        }
        __syncthreads();
    }

    #pragma unroll
    for (int i = 0; i < 4; i++) {
        int m = m0 + ty*4 + i;
        int bb = m >> 6, tt = m & 63;
        #pragma unroll
        for (int j = 0; j < 4; j++) {
            int n = n0 + tx*4 + j;
            C[(tt*512 + n)*256 + bb] = acc[i][j] + bias[n];
        }
    }
}

// ---------------------------------------------------------------------------
// Persistent recurrence: 128 CTAs = 32 clusters of 4, 8 batch rows/cluster.
// Each thread owns 4 consecutive output cols (float4 weight loads) and 8 rows
// packed as 4 fp32x2 accumulators. Partials reduced in conflict-free redT.
// GRU note: reference's `r * h @ Wh` == (r*h) @ Wh (left-assoc).
// SMEM floats: stochT 1024 | detT/x1T/x3T/rhT 4x4096 | zT 1024 |
//              redT 512*34=17408 | qbuf 640   -> 36480 floats = 145920 B
// ---------------------------------------------------------------------------
#define SMEM_REC (36480*4)

__global__ __launch_bounds__(512, 1) __cluster_dims__(4, 1, 1)
void rssm_recur(
    const float* __restrict__ prior_w1,   // 160x512
    const float* __restrict__ gru_wi,     // 512x1536
    const float* __restrict__ gru_wh,     // 512x1536
    const float* __restrict__ gru_b,      // 1536
    const float* __restrict__ post_w1,    // 1536x512 (rows 0..511 = det part)
    const float* __restrict__ post_w2,    // 512x256
    const float* __restrict__ post_b2,    // 256
    const float* __restrict__ noise_post, // B,T,128
    float* __restrict__ out)              // B,T,1152
{
    extern __shared__ __align__(16) float sm[];
    float* stochT = sm;            // [128][8] global cols
    float* detT   = sm + 1024;     // [512][8] global cols
    float* x1T    = sm + 5120;     // [512][8]
    float* x3T    = sm + 9216;     // [512][8]
    float* rhT    = sm + 13312;    // [512][8]
    float* zT     = sm + 17408;    // [128][8] LOCAL cols
    float* redT   = sm + 18432;    // 512 slots * 34
    float* qbuf   = sm + 35840;    // 64 * 10

    const int tid = threadIdx.x;
    uint32_t rank;
    asm("mov.u32 %0, %%cluster_ctarank;" : "=r"(rank));
    const int b0 = (blockIdx.x >> 2) * 8;
    const float* W1s = prior_w1 + 32*512;

    for (int i = tid; i < 1024; i += 512) stochT[i] = 0.f;
    for (int i = tid; i < 4096; i += 512) detT[i]   = 0.f;
    __syncthreads();
    CLUSTER_SYNC();

    for (int t = 0; t < T_; t++) {
        // ======== S0: x1 = elu(act_proj + stoch @ W1s), K=128 =============
        {
            const int cg = tid & 31, ks = tid >> 5;       // 16 ks x 8 k
            const int gc = (int)rank*128 + cg*4;
            u64 acc[4][4] = {};
            const float* wP = W1s + (ks*8)*512 + gc;
            const float* aP = stochT + (ks*8)*8;
            #pragma unroll
            for (int k = 0; k < 8; k++) {
                mac16(acc, aP, *(const float4*)wP);
                wP += 512; aP += 8;
            }
            storePartial(redT, ks*32 + cg, acc);
        }
        __syncthreads();
        if (tid < 128) {
            const int gc = (int)rank*128 + tid;
            float s[8] = {0,0,0,0,0,0,0,0};
            #pragma unroll
            for (int ks = 0; ks < 16; ks++) addP(s, redT, ks*32 + (tid>>2), tid&3);
            const float* ap = &g_act_proj[(t*512 + gc)*256 + b0];
            float4 p0 = *(const float4*)ap, p1 = *(const float4*)(ap+4);
            float4 lo = make_float4(elu_f(s[0]+p0.x), elu_f(s[1]+p0.y), elu_f(s[2]+p0.z), elu_f(s[3]+p0.w));
            float4 hi = make_float4(elu_f(s[4]+p1.x), elu_f(s[5]+p1.y), elu_f(s[6]+p1.z), elu_f(s[7]+p1.w));
            *(float4*)&x1T[gc*8]     = lo;
            *(float4*)&x1T[gc*8 + 4] = hi;
            bcast3(&x1T[gc*8], lo, hi, rank);
        }
        CLUSTER_SYNC();
        // ======== S1a: z & r gates, K=512 =================================
        {
            const int gate = tid >> 8;                    // 0=z, 1=r
            const int sub  = tid & 255;
            const int cg   = sub & 31;
            const int ks   = sub >> 5;                    // 8 ks x 64 k
            const int wcol = (gate ? 512 : 0) + (int)rank*128 + cg*4;
            u64 acc[4][4] = {};
            const float* wiP = gru_wi + (ks*64)*1536 + wcol;
            const float* whP = gru_wh + (ks*64)*1536 + wcol;
            const float* xP  = x1T  + (ks*64)*8;
            const float* dP  = detT + (ks*64)*8;
            #pragma unroll 4
            for (int k = 0; k < 64; k++) {
                mac16(acc, xP, *(const float4*)wiP);
                mac16(acc, dP, *(const float4*)whP);
                wiP += 1536; whP += 1536; xP += 8; dP += 8;
            }
            storePartial(redT, (gate*8 + ks)*32 + cg, acc);
        }
        __syncthreads();
        if (tid < 256) {
            const int half = tid >> 7;                    // 0=z, 1=r
            const int c    = tid & 127;
            const int gc   = (int)rank*128 + c;
            float s[8] = {0,0,0,0,0,0,0,0};
            #pragma unroll
            for (int ks = 0; ks < 8; ks++) addP(s, redT, (half*8 + ks)*32 + (c>>2), c&3);
            if (half == 0) {
                float b = gru_b[gc];
                #pragma unroll
                for (int r = 0; r < 8; r++) s[r] = sigm_f(s[r] + b);
                *(float4*)&zT[c*8]     = make_float4(s[0],s[1],s[2],s[3]);
                *(float4*)&zT[c*8 + 4] = make_float4(s[4],s[5],s[6],s[7]);
            } else {
                float b = gru_b[512 + gc];
                float4 dlo = *(const float4*)&detT[gc*8];
                float4 dhi = *(const float4*)&detT[gc*8 + 4];
                float4 lo = make_float4(sigm_f(s[0]+b)*dlo.x, sigm_f(s[1]+b)*dlo.y,
                                        sigm_f(s[2]+b)*dlo.z, sigm_f(s[3]+b)*dlo.w);
                float4 hi = make_float4(sigm_f(s[4]+b)*dhi.x, sigm_f(s[5]+b)*dhi.y,
                                        sigm_f(s[6]+b)*dhi.z, sigm_f(s[7]+b)*dhi.w);
                *(float4*)&rhT[gc*8]     = lo;
                *(float4*)&rhT[gc*8 + 4] = hi;
                bcast3(&rhT[gc*8], lo, hi, rank);
            }
        }
        CLUSTER_SYNC();
        // ======== S1c: ah = rh@Wh_a, ax = x1@Wi_a; det update =============
        {
            const int grp = tid >> 8;                     // 0=ah, 1=ax
            const int sub = tid & 255;
            const int cg  = sub & 31;
            const int ks  = sub >> 5;                     // 8 ks x 64 k
            const int wcol = 1024 + (int)rank*128 + cg*4;
            const float* W = grp ? gru_wi : gru_wh;
            const float* A = grp ? x1T : rhT;
            u64 acc[4][4] = {};
            const float* wP = W + (ks*64)*1536 + wcol;
            const float* aP = A + (ks*64)*8;
            #pragma unroll 4
            for (int k = 0; k < 64; k++) {
                mac16(acc, aP, *(const float4*)wP);
                wP += 1536; aP += 8;
            }
            storePartial(redT, (grp*8 + ks)*32 + cg, acc);
        }
        __syncthreads();
        if (tid < 128) {
            const int gc = (int)rank*128 + tid;
            float ah[8] = {0,0,0,0,0,0,0,0}, ax[8] = {0,0,0,0,0,0,0,0};
            #pragma unroll
            for (int ks = 0; ks < 8; ks++) {
                addP(ah, redT, ks*32 + (tid>>2), tid&3);
                addP(ax, redT, (8+ks)*32 + (tid>>2), tid&3);
            }
            float b = gru_b[1024 + gc];
            float z[8], d[8], dn[8];
            *(float4*)&z[0] = *(const float4*)&zT[tid*8];
            *(float4*)&z[4] = *(const float4*)&zT[tid*8 + 4];
            *(float4*)&d[0] = *(const float4*)&detT[gc*8];
            *(float4*)&d[4] = *(const float4*)&detT[gc*8 + 4];
            #pragma unroll
            for (int r = 0; r < 8; r++) {
                float av = tanhf(ax[r] + b + ah[r]);
                dn[r] = (1.f - z[r])*d[r] + z[r]*av;
            }
            float4 lo = make_float4(dn[0],dn[1],dn[2],dn[3]);
            float4 hi = make_float4(dn[4],dn[5],dn[6],dn[7]);
            *(float4*)&detT[gc*8]     = lo;
            *(float4*)&detT[gc*8 + 4] = hi;
            bcast3(&detT[gc*8], lo, hi, rank);
            #pragma unroll
            for (int r = 0; r < 8; r++)
                out[((b0 + r)*64 + t)*OUTW + 128 + gc] = dn[r];
        }
        CLUSTER_SYNC();
        // ======== S2: x3 = elu(obs_proj + det @ post_w1[:512]) ============
        {
            const int cg = tid & 31, ks = tid >> 5;       // 16 ks x 32 k
            const int gc = (int)rank*128 + cg*4;
            u64 acc[4][4] = {};
            const float* wP = post_w1 + (ks*32)*512 + gc;
            const float* aP = detT + (ks*32)*8;
            #pragma unroll 4
            for (int k = 0; k < 32; k++) {
                mac16(acc, aP, *(const float4*)wP);
                wP += 512; aP += 8;
            }
            storePartial(redT, ks*32 + cg, acc);
        }
        __syncthreads();
        if (tid < 128) {
            const int gc = (int)rank*128 + tid;
            float s[8] = {0,0,0,0,0,0,0,0};
            #pragma unroll
            for (int ks = 0; ks < 16; ks++) addP(s, redT, ks*32 + (tid>>2), tid&3);
            const float* op = &g_obs_proj[(t*512 + gc)*256 + b0];
            float4 p0 = *(const float4*)op, p1 = *(const float4*)(op+4);
            float4 lo = make_float4(elu_f(s[0]+p0.x), elu_f(s[1]+p0.y), elu_f(s[2]+p0.z), elu_f(s[3]+p0.w));
            float4 hi = make_float4(elu_f(s[4]+p1.x), elu_f(s[5]+p1.y), elu_f(s[6]+p1.z), elu_f(s[7]+p1.w));
            *(float4*)&x3T[gc*8]     = lo;
            *(float4*)&x3T[gc*8 + 4] = hi;
            bcast3(&x3T[gc*8], lo, hi, rank);
        }
        CLUSTER_SYNC();
        // ======== S3: q = x3 @ post_w2 + b2 (64 q-cols/CTA) ===============
        {
            const int cg16 = tid & 15, ks = tid >> 4;     // 32 ks x 16 k
            const int qcol = (cg16 < 8) ? ((int)rank*32 + cg16*4)
                                        : (128 + (int)rank*32 + (cg16-8)*4);
            u64 acc[4][4] = {};
            const float* wP = post_w2 + (ks*16)*256 + qcol;
            const float* aP = x3T + (ks*16)*8;
            #pragma unroll 4
            for (int k = 0; k < 16; k++) {
                mac16(acc, aP, *(const float4*)wP);
                wP += 256; aP += 8;
            }
            storePartial(redT, ks*16 + cg16, acc);
        }
        __syncthreads();
        if (tid < 64) {
            float s[8] = {0,0,0,0,0,0,0,0};
            #pragma unroll
            for (int ks = 0; ks < 32; ks++) addP(s, redT, ks*16 + (tid>>2), tid&3);
            #pragma unroll
            for (int r = 0; r < 8; r++) qbuf[tid*10 + r] = s[r];
        }
        __syncthreads();
        if (tid < 32) {
            const int j = (int)rank*32 + tid;
            float bm = post_b2[j], bs = post_b2[128 + j];
            float qm[8], qs[8], st[8];
            #pragma unroll
            for (int r = 0; r < 8; r++) {
                qm[r] = qbuf[tid*10 + r] + bm;
                qs[r] = softplus_f(qbuf[(32+tid)*10 + r] + bs) + 0.1f;
                float nq = noise_post[((b0 + r)*64 + t)*128 + j];
                st[r] = qm[r] + qs[r]*nq;
            }
            float4 lo = make_float4(st[0],st[1],st[2],st[3]);
            float4 hi = make_float4(st[4],st[5],st[6],st[7]);
            *(float4*)&stochT[j*8]     = lo;
            *(float4*)&stochT[j*8 + 4] = hi;
            bcast3(&stochT[j*8], lo, hi, rank);
            #pragma unroll
            for (int r = 0; r < 8; r++) {
                int base = ((b0 + r)*64 + t)*OUTW;
                out[base + j]        = st[r];
                out[base + 896 + j]  = qm[r];
                out[base + 1024 + j] = qs[r];
            }
        }
        CLUSTER_SYNC();
    }
}

// ---------------------------------------------------------------------------
// Deferred prior branch: M-tile 16 (smem 66KB -> 3 CTAs/SM)
// ---------------------------------------------------------------------------
#define MT 16
#define SMEM_PRI (2*MT*513*4)

__global__ __launch_bounds__(256) void prior_branch(
    const float* __restrict__ pw2, const float* __restrict__ pb2,
    const float* __restrict__ pw3, const float* __restrict__ pb3,
    float* __restrict__ out)
{
    extern __shared__ __align__(16) float sm2[];
    float* As = sm2;             // [16][513]
    float* Xp = sm2 + MT*513;    // [16][513]

    const int tid = threadIdx.x;
    const int m0  = blockIdx.x * MT;

    for (int i = tid; i < MT*512; i += 256) {
        int r = i >> 9, c = i & 511;
        As[r*513 + c] = out[(m0 + r)*OUTW + 128 + c];
    }
    __syncthreads();

    const int rw = tid >> 6;   // 0..3 -> rows rw*4..+3
    const int nc = tid & 63;

    {
        float acc[4][8];
        #pragma unroll
        for (int i = 0; i < 4; i++)
            #pragma unroll
            for (int j = 0; j < 8; j++) acc[i][j] = 0.f;
        #pragma unroll 4
        for (int k = 0; k < 512; k++) {
            float a[4];
            #pragma unroll
            for (int i = 0; i < 4; i++) a[i] = As[(rw*4 + i)*513 + k];
            float4 w0 = *(const float4*)&pw2[k*512 + nc*8];
            float4 w1 = *(const float4*)&pw2[k*512 + nc*8 + 4];
            float w[8] = {w0.x, w0.y, w0.z, w0.w, w1.x, w1.y, w1.z, w1.w};
            #pragma unroll
            for (int i = 0; i < 4; i++)
                #pragma unroll
                for (int j = 0; j < 8; j++) acc[i][j] += a[i]*w[j];
        }
        #pragma unroll
        for (int i = 0; i < 4; i++)
            #pragma unroll
            for (int j = 0; j < 8; j++)
                Xp[(rw*4 + i)*513 + nc*8 + j] = elu_f(acc[i][j] + pb2[nc*8 + j]);
    }
    __syncthreads();
    {
        float acc[4][4];
        #pragma unroll
        for (int i = 0; i < 4; i++)
            #pragma unroll
            for (int j = 0; j < 4; j++) acc[i][j] = 0.f;
        #pragma unroll 4
        for (int k = 0; k < 512; k++) {
            float a[4];
            #pragma unroll
            for (int i = 0; i < 4; i++) a[i] = Xp[(rw*4 + i)*513 + k];
            float4 w4 = *(const float4*)&pw3[k*256 + nc*4];
            float w[4] = {w4.x, w4.y, w4.z, w4.w};
            #pragma unroll
            for (int i = 0; i < 4; i++)
                #pragma unroll
                for (int j = 0; j < 4; j++) acc[i][j] += a[i]*w[j];
        }
        #pragma unroll
        for (int i = 0; i < 4; i++) {
            int m = m0 + rw*4 + i;
            #pragma unroll
            for (int j = 0; j < 4; j++) {
                int c = nc*4 + j;
                float v = acc[i][j] + pb3[c];
                if (c < 128) out[m*OUTW + 640 + c] = v;
                else         out[m*OUTW + 768 + (c - 128)] = softplus_f(v) + 0.1f;
            }
        }
    }
}

// ---------------------------------------------------------------------------
extern "C" void kernel_launch(void* const* d_in, const int* in_sizes, int n_in,
                              void* d_out, int out_size)
{
    const float* observations = (const float*)d_in[0];
    const float* actions      = (const float*)d_in[1];
    // d_in[2] = noise_prior: unused (prior sample is dead in the reference)
    const float* noise_post   = (const float*)d_in[3];
    const float* prior_w1     = (const float*)d_in[4];
    const float* prior_b1     = (const float*)d_in[5];
    const float* gru_wi       = (const float*)d_in[6];
    const float* gru_wh       = (const float*)d_in[7];
    const float* gru_b        = (const float*)d_in[8];
    const float* prior_w2     = (const float*)d_in[9];
    const float* prior_b2     = (const float*)d_in[10];
    const float* prior_w3     = (const float*)d_in[11];
    const float* prior_b3     = (const float*)d_in[12];
    const float* post_w1      = (const float*)d_in[13];
    const float* post_b1      = (const float*)d_in[14];
    const float* post_w2      = (const float*)d_in[15];
    const float* post_b2      = (const float*)d_in[16];
    float* out = (float*)d_out;

    float *actp, *obsp;
    cudaGetSymbolAddress((void**)&actp, g_act_proj);
    cudaGetSymbolAddress((void**)&obsp, g_obs_proj);

    cudaFuncSetAttribute(rssm_recur, cudaFuncAttributeMaxDynamicSharedMemorySize, SMEM_REC);
    cudaFuncSetAttribute(prior_branch, cudaFuncAttributeMaxDynamicSharedMemorySize, SMEM_PRI);

    // Batched precompute (prerequisites of the scan), transposed outputs
    proj_gemm<<<dim3(8, BT/64), 256>>>(actions, prior_w1, prior_b1, actp, ACTD);
    proj_gemm<<<dim3(8, BT/64), 256>>>(observations, post_w1 + 512*512, post_b1, obsp, OBSD);
    // tiny dummy to shift ncu's -s5 capture ordinal onto rssm_recur
    ncu_align_dummy<<<1, 32>>>();
    // Sequential recurrence: 32 clusters x 4 CTAs x 512 threads
    rssm_recur<<<128, 512, SMEM_REC>>>(prior_w1, gru_wi, gru_wh, gru_b,
                                       post_w1, post_w2, post_b2, noise_post, out);
    // Deferred prior head, batched over all B*T rows
    prior_branch<<<BT/MT, 256, SMEM_PRI>>>(prior_w2, prior_b2, prior_w3, prior_b3, out);
}

// round 7
// speedup vs baseline: 4.8800x; 1.0096x over previous
#include <cuda_runtime.h>
#include <math.h>
#include <stdint.h>

#define B_    256
#define T_    64
#define STOCH 128
#define DETD  512
#define HIDD  512
#define OBSD  1024
#define ACTD  32
#define BT    (B_*T_)
#define OUTW  1152

typedef unsigned long long u64;

// Scratch (device globals). TRANSPOSED layout: [t][c][b]  (b fastest)
__device__ float g_act_proj[T_*DETD*B_];
__device__ float g_obs_proj[T_*HIDD*B_];
__device__ float g_dummy[32];

__device__ __forceinline__ float elu_f(float x)      { return x > 0.f ? x : (__expf(x) - 1.f); }
__device__ __forceinline__ float sigm_f(float x)     { return 1.f/(1.f+__expf(-x)); }
__device__ __forceinline__ float softplus_f(float x) { return fmaxf(x,0.f) + log1pf(__expf(-fabsf(x))); }

__device__ __forceinline__ uint32_t smem_u32(const void* p) {
    uint32_t a;
    asm("{ .reg .u64 t; cvta.to.shared.u64 t, %1; cvt.u32.u64 %0, t; }" : "=r"(a) : "l"(p));
    return a;
}
// packed fp32x2 FMA: d.lo += a.lo*b.lo ; d.hi += a.hi*b.hi
__device__ __forceinline__ void fma2(u64& d, u64 a, u64 b) {
    asm("fma.rn.f32x2 %0, %1, %2, %0;" : "+l"(d) : "l"(a), "l"(b));
}
__device__ __forceinline__ u64 pack2(float w) {
    u64 r; unsigned int u = __float_as_uint(w);
    asm("mov.b64 %0, {%1, %1};" : "=l"(r) : "r"(u));
    return r;
}
// 4 cols x 4 row-pairs MAC block: acc[c][rp] += act[rp] * w4[c]
// activations loaded as 2x LDS.128 (broadcast)
__device__ __forceinline__ void mac16(u64 (&acc)[4][4], const float* actcol, float4 w4) {
    ulonglong2 p0 = *(const ulonglong2*)(actcol);
    ulonglong2 p1 = *(const ulonglong2*)(actcol + 4);
    u64 a0 = p0.x, a1 = p0.y, a2 = p1.x, a3 = p1.y;
    u64 w;
    w = pack2(w4.x); fma2(acc[0][0],a0,w); fma2(acc[0][1],a1,w); fma2(acc[0][2],a2,w); fma2(acc[0][3],a3,w);
    w = pack2(w4.y); fma2(acc[1][0],a0,w); fma2(acc[1][1],a1,w); fma2(acc[1][2],a2,w); fma2(acc[1][3],a3,w);
    w = pack2(w4.z); fma2(acc[2][0],a0,w); fma2(acc[2][1],a1,w); fma2(acc[2][2],a2,w); fma2(acc[2][3],a3,w);
    w = pack2(w4.w); fma2(acc[3][0],a0,w); fma2(acc[3][1],a1,w); fma2(acc[3][2],a2,w); fma2(acc[3][3],a3,w);
}
#define RSLOT 34
__device__ __forceinline__ void storePartial(float* redT, int slot, u64 (&acc)[4][4]) {
    u64* rd = (u64*)(redT + slot*RSLOT);
    #pragma unroll
    for (int c = 0; c < 4; c++)
        #pragma unroll
        for (int rp = 0; rp < 4; rp++) rd[c*4 + rp] = acc[c][rp];
}
// half-row (4 rows) partial add
__device__ __forceinline__ void addPh(float s[4], const float* redT, int slot, int c4, int rh) {
    const float2* p = (const float2*)(redT + slot*RSLOT + c4*8 + rh*4);
    float2 v0 = p[0], v1 = p[1];
    s[0]+=v0.x; s[1]+=v0.y; s[2]+=v1.x; s[3]+=v1.y;
}
// store one float4 into the 3 peer CTAs' SMEM at the same offset
__device__ __forceinline__ void bcast3h(const float* dst, float4 v, uint32_t rank) {
    uint32_t la = smem_u32(dst);
    #pragma unroll
    for (uint32_t pr = 0; pr < 4; pr++) {
        if (pr == rank) continue;
        uint32_t ra;
        asm("mapa.shared::cluster.u32 %0, %1, %2;" : "=r"(ra) : "r"(la), "r"(pr));
        asm volatile("st.shared::cluster.v4.f32 [%0], {%1,%2,%3,%4};"
                     :: "r"(ra), "f"(v.x), "f"(v.y), "f"(v.z), "f"(v.w) : "memory");
    }
}
#define CLUSTER_SYNC() do { \
    asm volatile("barrier.cluster.arrive.aligned;" ::: "memory"); \
    asm volatile("barrier.cluster.wait.aligned;"   ::: "memory"); \
} while (0)

__global__ void ncu_align_dummy() { g_dummy[threadIdx.x & 31] = (float)threadIdx.x; }

// ---------------------------------------------------------------------------
// Batched projection GEMM with TRANSPOSED output: C[(t*512+n)*256 + b]
// fp32x2 inner: rows scalar-packed, col-pairs native from float4 loads.
// ---------------------------------------------------------------------------
__global__ __launch_bounds__(256) void proj_gemm(
    const float* __restrict__ A, const float* __restrict__ W,
    const float* __restrict__ bias, float* __restrict__ C, int K)
{
    __shared__ __align__(16) float Ast[16][68];
    __shared__ __align__(16) float Bs[16][64];

    const int tid = threadIdx.x;
    const int m0 = blockIdx.y * 64;
    const int n0 = blockIdx.x * 64;
    const int tx = tid & 15, ty = tid >> 4;

    const int arow = tid >> 2;
    const int avec = (tid & 3) * 4;
    const int bk   = tid >> 4;
    const int bn   = (tid & 15) * 4;

    u64 acc[4][2] = {};   // [row][colpair]

    for (int k0 = 0; k0 < K; k0 += 16) {
        float4 av = *(const float4*)&A[(m0 + arow) * K + k0 + avec];
        Ast[avec+0][arow] = av.x;
        Ast[avec+1][arow] = av.y;
        Ast[avec+2][arow] = av.z;
        Ast[avec+3][arow] = av.w;
        float4 bv = *(const float4*)&W[(k0 + bk) * 512 + n0 + bn];
        *(float4*)&Bs[bk][bn] = bv;
        __syncthreads();
        #pragma unroll
        for (int kk = 0; kk < 16; kk++) {
            float4 a4 = *(const float4*)&Ast[kk][ty*4];
            ulonglong2 wv = *(const ulonglong2*)&Bs[kk][tx*4];
            u64 pa0 = pack2(a4.x), pa1 = pack2(a4.y), pa2 = pack2(a4.z), pa3 = pack2(a4.w);
            fma2(acc[0][0], pa0, wv.x); fma2(acc[0][1], pa0, wv.y);
            fma2(acc[1][0], pa1, wv.x); fma2(acc[1][1], pa1, wv.y);
            fma2(acc[2][0], pa2, wv.x); fma2(acc[2][1], pa2, wv.y);
            fma2(acc[3][0], pa3, wv.x); fma2(acc[3][1], pa3, wv.y);
        }
        __syncthreads();
    }

    #pragma unroll
    for (int i = 0; i < 4; i++) {
        int m = m0 + ty*4 + i;
        int bb = m >> 6, tt = m & 63;
        #pragma unroll
        for (int cp = 0; cp < 2; cp++) {
            float2 v = *(float2*)&acc[i][cp];
            int n = n0 + tx*4 + cp*2;
            C[(tt*512 + n)*256 + bb]     = v.x + bias[n];
            C[(tt*512 + n + 1)*256 + bb] = v.y + bias[n+1];
        }
    }
}

// ---------------------------------------------------------------------------
// Persistent recurrence: 128 CTAs = 32 clusters of 4, 8 batch rows/cluster.
// ---------------------------------------------------------------------------
#define SMEM_REC (36480*4)

__global__ __launch_bounds__(512, 1) __cluster_dims__(4, 1, 1)
void rssm_recur(
    const float* __restrict__ prior_w1,   // 160x512
    const float* __restrict__ gru_wi,     // 512x1536
    const float* __restrict__ gru_wh,     // 512x1536
    const float* __restrict__ gru_b,      // 1536
    const float* __restrict__ post_w1,    // 1536x512
    const float* __restrict__ post_w2,    // 512x256
    const float* __restrict__ post_b2,    // 256
    const float* __restrict__ noise_post, // B,T,128
    float* __restrict__ out)              // B,T,1152
{
    extern __shared__ __align__(16) float sm[];
    float* stochT = sm;            // [128][8] global cols
    float* detT   = sm + 1024;     // [512][8]
    float* x1T    = sm + 5120;     // [512][8]
    float* x3T    = sm + 9216;     // [512][8]
    float* rhT    = sm + 13312;    // [512][8]
    float* zT     = sm + 17408;    // [128][8] LOCAL cols
    float* redT   = sm + 18432;    // 512 slots * 34
    float* qbuf   = sm + 35840;    // 64 * 10

    const int tid = threadIdx.x;
    uint32_t rank;
    asm("mov.u32 %0, %%cluster_ctarank;" : "=r"(rank));
    const int b0 = (blockIdx.x >> 2) * 8;
    const float* W1s = prior_w1 + 32*512;

    // ---- t-invariant per-thread decompositions & base pointers ----
    // S0/S2 (cols 128, ksplit 16)
    const int cgA = tid & 31, ksA = tid >> 5;
    const int gcA = (int)rank*128 + cgA*4;
    const int slotA = ksA*32 + cgA;
    const float* wS0 = W1s     + (ksA*8)*512  + gcA;
    const float* wS2 = post_w1 + (ksA*32)*512 + gcA;
    const float* aS0 = stochT + ksA*64;
    const float* aS2 = detT   + ksA*256;
    // S1a / S1c (2 groups x 32 cg x 8 ks)
    const int grpB = tid >> 8, subB = tid & 255, cgB = subB & 31, ksB = subB >> 5;
    const int wcolB = (grpB ? 512 : 0) + (int)rank*128 + cgB*4;
    const int wcolC = 1024 + (int)rank*128 + cgB*4;
    const float* wiB = gru_wi + (ksB*64)*1536 + wcolB;
    const float* whB = gru_wh + (ksB*64)*1536 + wcolB;
    const float* wC  = (grpB ? gru_wi : gru_wh) + (ksB*64)*1536 + wcolC;
    const float* aBx = x1T  + ksB*512;
    const float* aBd = detT + ksB*512;
    const float* aC  = (grpB ? x1T : rhT) + ksB*512;
    const int slotB = (grpB*8 + ksB)*32 + cgB;
    // S3 (16 col-groups x 32 ks)
    const int cg16 = tid & 15, ksE = tid >> 4;
    const int qcolE = (cg16 < 8) ? ((int)rank*32 + cg16*4)
                                 : (128 + (int)rank*32 + (cg16-8)*4);
    const float* wE = post_w2 + (ksE*16)*256 + qcolE;
    const float* aE = x3T + ksE*128;
    const int slotE = ksE*16 + cg16;

    for (int i = tid; i < 1024; i += 512) stochT[i] = 0.f;
    for (int i = tid; i < 4096; i += 512) detT[i]   = 0.f;
    __syncthreads();
    CLUSTER_SYNC();

    for (int t = 0; t < T_; t++) {
        // ======== S0: x1 = elu(act_proj + stoch @ W1s), K=128 =============
        {
            u64 acc[4][4] = {};
            const float* wP = wS0;
            const float* aP = aS0;
            #pragma unroll
            for (int k = 0; k < 8; k++) {
                mac16(acc, aP, *(const float4*)wP);
                wP += 512; aP += 8;
            }
            storePartial(redT, slotA, acc);
        }
        __syncthreads();
        if (tid < 256) {
            const int c = tid & 127, rh = tid >> 7;
            const int gc = (int)rank*128 + c;
            float s[4] = {0,0,0,0};
            #pragma unroll
            for (int ks = 0; ks < 16; ks++) addPh(s, redT, ks*32 + (c>>2), c&3, rh);
            const float* ap = &g_act_proj[(t*512 + gc)*256 + b0 + rh*4];
            float4 p = *(const float4*)ap;
            float4 v = make_float4(elu_f(s[0]+p.x), elu_f(s[1]+p.y), elu_f(s[2]+p.z), elu_f(s[3]+p.w));
            *(float4*)&x1T[gc*8 + rh*4] = v;
            bcast3h(&x1T[gc*8 + rh*4], v, rank);
        }
        CLUSTER_SYNC();
        // ======== S1a: z & r gates, K=512 =================================
        {
            u64 acc[4][4] = {};
            const float* wiP = wiB;
            const float* whP = whB;
            const float* xP  = aBx;
            const float* dP  = aBd;
            #pragma unroll 4
            for (int k = 0; k < 64; k++) {
                mac16(acc, xP, *(const float4*)wiP);
                mac16(acc, dP, *(const float4*)whP);
                wiP += 1536; whP += 1536; xP += 8; dP += 8;
            }
            storePartial(redT, slotB, acc);
        }
        __syncthreads();
        {
            const int half = tid >> 8;            // 0=z, 1=r
            const int rh   = (tid >> 7) & 1;
            const int c    = tid & 127;
            const int gc   = (int)rank*128 + c;
            float s[4] = {0,0,0,0};
            #pragma unroll
            for (int ks = 0; ks < 8; ks++) addPh(s, redT, (half*8 + ks)*32 + (c>>2), c&3, rh);
            if (half == 0) {
                float b = gru_b[gc];
                float4 v = make_float4(sigm_f(s[0]+b), sigm_f(s[1]+b), sigm_f(s[2]+b), sigm_f(s[3]+b));
                *(float4*)&zT[c*8 + rh*4] = v;
            } else {
                float b = gru_b[512 + gc];
                float4 d = *(const float4*)&detT[gc*8 + rh*4];
                float4 v = make_float4(sigm_f(s[0]+b)*d.x, sigm_f(s[1]+b)*d.y,
                                       sigm_f(s[2]+b)*d.z, sigm_f(s[3]+b)*d.w);
                *(float4*)&rhT[gc*8 + rh*4] = v;
                bcast3h(&rhT[gc*8 + rh*4], v, rank);
            }
        }
        CLUSTER_SYNC();
        // ======== S1c: ah = rh@Wh_a (grp0), ax = x1@Wi_a (grp1) ===========
        {
            u64 acc[4][4] = {};
            const float* wP = wC;
            const float* aP = aC;
            #pragma unroll 4
            for (int k = 0; k < 64; k++) {
                mac16(acc, aP, *(const float4*)wP);
                wP += 1536; aP += 8;
            }
            storePartial(redT, slotB, acc);
        }
        __syncthreads();
        if (tid < 256) {
            const int c = tid & 127, rh = tid >> 7;
            const int gc = (int)rank*128 + c;
            float ah[4] = {0,0,0,0}, ax[4] = {0,0,0,0};
            #pragma unroll
            for (int ks = 0; ks < 8; ks++) {
                addPh(ah, redT, ks*32 + (c>>2), c&3, rh);
                addPh(ax, redT, (8+ks)*32 + (c>>2), c&3, rh);
            }
            float b = gru_b[1024 + gc];
            float4 z4 = *(const float4*)&zT[c*8 + rh*4];
            float4 d4 = *(const float4*)&detT[gc*8 + rh*4];
            float z[4] = {z4.x, z4.y, z4.z, z4.w};
            float d[4] = {d4.x, d4.y, d4.z, d4.w};
            float dn[4];
            #pragma unroll
            for (int r = 0; r < 4; r++) {
                float av = tanhf(ax[r] + b + ah[r]);
                dn[r] = (1.f - z[r])*d[r] + z[r]*av;
            }
            float4 v = make_float4(dn[0],dn[1],dn[2],dn[3]);
            *(float4*)&detT[gc*8 + rh*4] = v;
            bcast3h(&detT[gc*8 + rh*4], v, rank);
            #pragma unroll
            for (int r = 0; r < 4; r++)
                out[((b0 + rh*4 + r)*64 + t)*OUTW + 128 + gc] = dn[r];
        }
        CLUSTER_SYNC();
        // ======== S2: x3 = elu(obs_proj + det @ post_w1[:512]) ============
        {
            u64 acc[4][4] = {};
            const float* wP = wS2;
            const float* aP = aS2;
            #pragma unroll 4
            for (int k = 0; k < 32; k++) {
                mac16(acc, aP, *(const float4*)wP);
                wP += 512; aP += 8;
            }
            storePartial(redT, slotA, acc);
        }
        __syncthreads();
        if (tid < 256) {
            const int c = tid & 127, rh = tid >> 7;
            const int gc = (int)rank*128 + c;
            float s[4] = {0,0,0,0};
            #pragma unroll
            for (int ks = 0; ks < 16; ks++) addPh(s, redT, ks*32 + (c>>2), c&3, rh);
            const float* op = &g_obs_proj[(t*512 + gc)*256 + b0 + rh*4];
            float4 p = *(const float4*)op;
            float4 v = make_float4(elu_f(s[0]+p.x), elu_f(s[1]+p.y), elu_f(s[2]+p.z), elu_f(s[3]+p.w));
            *(float4*)&x3T[gc*8 + rh*4] = v;
            bcast3h(&x3T[gc*8 + rh*4], v, rank);
        }
        CLUSTER_SYNC();
        // ======== S3: q = x3 @ post_w2 + b2 (64 q-cols/CTA) ===============
        {
            u64 acc[4][4] = {};
            const float* wP = wE;
            const float* aP = aE;
            #pragma unroll 4
            for (int k = 0; k < 16; k++) {
                mac16(acc, aP, *(const float4*)wP);
                wP += 256; aP += 8;
            }
            storePartial(redT, slotE, acc);
        }
        __syncthreads();
        if (tid < 128) {
            const int l = tid & 63, rh = tid >> 6;
            float s[4] = {0,0,0,0};
            #pragma unroll
            for (int ks = 0; ks < 32; ks++) addPh(s, redT, ks*16 + (l>>2), l&3, rh);
            #pragma unroll
            for (int r = 0; r < 4; r++) qbuf[l*10 + rh*4 + r] = s[r];
        }
        __syncthreads();
        if (tid < 64) {
            const int j32 = tid & 31, rh = tid >> 5;
            const int j = (int)rank*32 + j32;
            float bm = post_b2[j], bs = post_b2[128 + j];
            float qm[4], qs[4], st[4];
            #pragma unroll
            for (int r = 0; r < 4; r++) {
                qm[r] = qbuf[j32*10 + rh*4 + r] + bm;
                qs[r] = softplus_f(qbuf[(32+j32)*10 + rh*4 + r] + bs) + 0.1f;
                float nq = noise_post[((b0 + rh*4 + r)*64 + t)*128 + j];
                st[r] = qm[r] + qs[r]*nq;
            }
            float4 v = make_float4(st[0],st[1],st[2],st[3]);
            *(float4*)&stochT[j*8 + rh*4] = v;
            bcast3h(&stochT[j*8 + rh*4], v, rank);
            #pragma unroll
            for (int r = 0; r < 4; r++) {
                int base = ((b0 + rh*4 + r)*64 + t)*OUTW;
                out[base + j]        = st[r];
                out[base + 896 + j]  = qm[r];
                out[base + 1024 + j] = qs[r];
            }
        }
        CLUSTER_SYNC();
    }
}

// ---------------------------------------------------------------------------
// Deferred prior branch: M-tile 16, fp32x2 inner loops
// ---------------------------------------------------------------------------
#define MT 16
#define SMEM_PRI (2*MT*513*4)

__global__ __launch_bounds__(256) void prior_branch(
    const float* __restrict__ pw2, const float* __restrict__ pb2,
    const float* __restrict__ pw3, const float* __restrict__ pb3,
    float* __restrict__ out)
{
    extern __shared__ __align__(16) float sm2[];
    float* As = sm2;             // [16][513]
    float* Xp = sm2 + MT*513;    // [16][513]

    const int tid = threadIdx.x;
    const int m0  = blockIdx.x * MT;

    for (int i = tid; i < MT*512; i += 256) {
        int r = i >> 9, c = i & 511;
        As[r*513 + c] = out[(m0 + r)*OUTW + 128 + c];
    }
    __syncthreads();

    const int rw = tid >> 6;   // 0..3 -> rows rw*4..+3
    const int nc = tid & 63;   // 8 cols

    {   // GEMM1: Xp = elu(As @ pw2 + b2)
        u64 acc[4][4] = {};    // [row][colpair]
        #pragma unroll 4
        for (int k = 0; k < 512; k++) {
            u64 pa0 = pack2(As[(rw*4 + 0)*513 + k]);
            u64 pa1 = pack2(As[(rw*4 + 1)*513 + k]);
            u64 pa2 = pack2(As[(rw*4 + 2)*513 + k]);
            u64 pa3 = pack2(As[(rw*4 + 3)*513 + k]);
            ulonglong2 w0 = *(const ulonglong2*)&pw2[k*512 + nc*8];
            ulonglong2 w1 = *(const ulonglong2*)&pw2[k*512 + nc*8 + 4];
            fma2(acc[0][0],pa0,w0.x); fma2(acc[0][1],pa0,w0.y); fma2(acc[0][2],pa0,w1.x); fma2(acc[0][3],pa0,w1.y);
            fma2(acc[1][0],pa1,w0.x); fma2(acc[1][1],pa1,w0.y); fma2(acc[1][2],pa1,w1.x); fma2(acc[1][3],pa1,w1.y);
            fma2(acc[2][0],pa2,w0.x); fma2(acc[2][1],pa2,w0.y); fma2(acc[2][2],pa2,w1.x); fma2(acc[2][3],pa2,w1.y);
            fma2(acc[3][0],pa3,w0.x); fma2(acc[3][1],pa3,w0.y); fma2(acc[3][2],pa3,w1.x); fma2(acc[3][3],pa3,w1.y);
        }
        #pragma unroll
        for (int i = 0; i < 4; i++)
            #pragma unroll
            for (int cp = 0; cp < 4; cp++) {
                float2 v = *(float2*)&acc[i][cp];
                int c = nc*8 + cp*2;
                Xp[(rw*4 + i)*513 + c]     = elu_f(v.x + pb2[c]);
                Xp[(rw*4 + i)*513 + c + 1] = elu_f(v.y + pb2[c+1]);
            }
    }
    __syncthreads();
    {   // GEMM2: [16][256] -> pm/ps
        u64 acc[4][2] = {};
        #pragma unroll 4
        for (int k = 0; k < 512; k++) {
            u64 pa0 = pack2(Xp[(rw*4 + 0)*513 + k]);
            u64 pa1 = pack2(Xp[(rw*4 + 1)*513 + k]);
            u64 pa2 = pack2(Xp[(rw*4 + 2)*513 + k]);
            u64 pa3 = pack2(Xp[(rw*4 + 3)*513 + k]);
            ulonglong2 w = *(const ulonglong2*)&pw3[k*256 + nc*4];
            fma2(acc[0][0],pa0,w.x); fma2(acc[0][1],pa0,w.y);
            fma2(acc[1][0],pa1,w.x); fma2(acc[1][1],pa1,w.y);
            fma2(acc[2][0],pa2,w.x); fma2(acc[2][1],pa2,w.y);
            fma2(acc[3][0],pa3,w.x); fma2(acc[3][1],pa3,w.y);
        }
        #pragma unroll
        for (int i = 0; i < 4; i++) {
            int m = m0 + rw*4 + i;
            #pragma unroll
            for (int cp = 0; cp < 2; cp++) {
                float2 v = *(float2*)&acc[i][cp];
                #pragma unroll
                for (int e = 0; e < 2; e++) {
                    int c = nc*4 + cp*2 + e;
                    float val = (e ? v.y : v.x) + pb3[c];
                    if (c < 128) out[m*OUTW + 640 + c] = val;
                    else         out[m*OUTW + 768 + (c - 128)] = softplus_f(val) + 0.1f;
                }
            }
        }
    }
}

// ---------------------------------------------------------------------------
extern "C" void kernel_launch(void* const* d_in, const int* in_sizes, int n_in,
                              void* d_out, int out_size)
{
    const float* observations = (const float*)d_in[0];
    const float* actions      = (const float*)d_in[1];
    // d_in[2] = noise_prior: unused (prior sample is dead in the reference)
    const float* noise_post   = (const float*)d_in[3];
    const float* prior_w1     = (const float*)d_in[4];
    const float* prior_b1     = (const float*)d_in[5];
    const float* gru_wi       = (const float*)d_in[6];
    const float* gru_wh       = (const float*)d_in[7];
    const float* gru_b        = (const float*)d_in[8];
    const float* prior_w2     = (const float*)d_in[9];
    const float* prior_b2     = (const float*)d_in[10];
    const float* prior_w3     = (const float*)d_in[11];
    const float* prior_b3     = (const float*)d_in[12];
    const float* post_w1      = (const float*)d_in[13];
    const float* post_b1      = (const float*)d_in[14];
    const float* post_w2      = (const float*)d_in[15];
    const float* post_b2      = (const float*)d_in[16];
    float* out = (float*)d_out;

    float *actp, *obsp;
    cudaGetSymbolAddress((void**)&actp, g_act_proj);
    cudaGetSymbolAddress((void**)&obsp, g_obs_proj);

    cudaFuncSetAttribute(rssm_recur, cudaFuncAttributeMaxDynamicSharedMemorySize, SMEM_REC);
    cudaFuncSetAttribute(prior_branch, cudaFuncAttributeMaxDynamicSharedMemorySize, SMEM_PRI);

    // Batched precompute (prerequisites of the scan), transposed outputs
    proj_gemm<<<dim3(8, BT/64), 256>>>(actions, prior_w1, prior_b1, actp, ACTD);
    proj_gemm<<<dim3(8, BT/64), 256>>>(observations, post_w1 + 512*512, post_b1, obsp, OBSD);
    // tiny dummy to keep ncu's -s5 capture ordinal on rssm_recur
    ncu_align_dummy<<<1, 32>>>();
    // Sequential recurrence: 32 clusters x 4 CTAs x 512 threads
    rssm_recur<<<128, 512, SMEM_REC>>>(prior_w1, gru_wi, gru_wh, gru_b,
                                       post_w1, post_w2, post_b2, noise_post, out);
    // Deferred prior head, batched over all B*T rows
    prior_branch<<<BT/MT, 256, SMEM_PRI>>>(prior_w2, prior_b2, prior_w3, prior_b3, out);
}